// round 12
// baseline (speedup 1.0000x reference)
#include <cuda_runtime.h>
#include <cuda_fp16.h>
#include <math.h>
#include <stdint.h>

#define B_   2
#define S_   2048
#define H_   2048
#define NH_  16
#define HD_  128
#define TS_  512
#define ROWS (B_*S_)        // 4096
#define KIDX 460

// ------------------------- mma.sync helpers (baseline PTX) -----------------
__device__ __forceinline__ uint32_t smem_u32(const void* p) {
    uint32_t a;
    asm("{ .reg .u64 t; cvta.to.shared.u64 t,%1; cvt.u32.u64 %0,t; }" : "=r"(a) : "l"(p));
    return a;
}
__device__ __forceinline__ void ldsm4(uint32_t* r, uint32_t addr) {
    asm volatile("ldmatrix.sync.aligned.m8n8.x4.shared.b16 {%0,%1,%2,%3},[%4];"
        : "=r"(r[0]), "=r"(r[1]), "=r"(r[2]), "=r"(r[3]) : "r"(addr));
}
__device__ __forceinline__ void ldsm4t(uint32_t* r, uint32_t addr) {
    asm volatile("ldmatrix.sync.aligned.m8n8.x4.trans.shared.b16 {%0,%1,%2,%3},[%4];"
        : "=r"(r[0]), "=r"(r[1]), "=r"(r[2]), "=r"(r[3]) : "r"(addr));
}
__device__ __forceinline__ void mma16816(float* c, const uint32_t* a, const uint32_t* b) {
    asm volatile(
        "mma.sync.aligned.m16n8k16.row.col.f32.f16.f16.f32 "
        "{%0,%1,%2,%3},{%4,%5,%6,%7},{%8,%9},{%0,%1,%2,%3};"
        : "+f"(c[0]), "+f"(c[1]), "+f"(c[2]), "+f"(c[3])
        : "r"(a[0]), "r"(a[1]), "r"(a[2]), "r"(a[3]), "r"(b[0]), "r"(b[1]));
}
__device__ __forceinline__ uint32_t pack_h2(float a, float b) {
    __half ha = __float2half_rn(a), hb = __float2half_rn(b);
    return (uint32_t)__half_as_ushort(ha) | ((uint32_t)__half_as_ushort(hb) << 16);
}
__device__ __forceinline__ void split_store(float v, __half* hi, __half* lo, size_t idx) {
    __half h = __float2half_rn(v);
    hi[idx] = h;
    lo[idx] = __float2half_rn(v - __half2float(h));
}
__device__ __forceinline__ void cpa16(uint32_t dst, const void* src) {
    asm volatile("cp.async.cg.shared.global [%0],[%1],16;" :: "r"(dst), "l"(src));
}
#define CPA_COMMIT() asm volatile("cp.async.commit_group;" ::: "memory")
#define CPA_WAIT1()  asm volatile("cp.async.wait_group 1;" ::: "memory")
#define CPA_WAIT0()  asm volatile("cp.async.wait_group 0;" ::: "memory")

// ---------------- scratch (device globals) ---------------------------------
__device__ float g_ts[(size_t)ROWS * TS_];
__device__ float g_add[(size_t)ROWS * 4096];
__device__ float g_qkv[(size_t)ROWS * 6144];
__device__ float g_invf[64];

__device__ __half g_Ahi[(size_t)ROWS * H_];     // hidden, later attn-out
__device__ __half g_Alo[(size_t)ROWS * H_];
__device__ __half g_tsHi[(size_t)ROWS * TS_];
__device__ __half g_tsLo[(size_t)ROWS * TS_];
__device__ __half g_Qhi[(size_t)ROWS * H_];
__device__ __half g_Qlo[(size_t)ROWS * H_];
__device__ __half g_Khi[(size_t)ROWS * H_];     // fp16-rounded (B operand)
__device__ __half g_Vhi[(size_t)ROWS * H_];     // fp16-rounded (B operand)

#define WOFF_Q  ((size_t)0)
#define WOFF_K  ((size_t)4194304)
#define WOFF_V  ((size_t)8388608)
#define WOFF_O  ((size_t)12582912)
#define WOFF_TS ((size_t)16777216)
#define WOFF_OR ((size_t)17825792)
#define WTOTAL  ((size_t)19922944)
__device__ __half g_WHi[WTOTAL];                // weights fp16-rounded (B operands)

__global__ void init_invf_kernel() {
    int d = threadIdx.x;
    if (d < 64) g_invf[d] = (float)exp(-(double)d * (9.210340371976184 / 64.0));
}

// ---------------- convert kernels ------------------------------------------
__global__ void convertA_kernel(const float* __restrict__ src,
                                __half* __restrict__ hi,
                                __half* __restrict__ lo, int n4)
{
    int i = blockIdx.x * blockDim.x + threadIdx.x;
    if (i >= n4) return;
    float4 v = ((const float4*)src)[i];
    __half h0 = __float2half_rn(v.x);
    __half h1 = __float2half_rn(v.y);
    __half h2 = __float2half_rn(v.z);
    __half h3 = __float2half_rn(v.w);
    __half l0 = __float2half_rn(v.x - __half2float(h0));
    __half l1 = __float2half_rn(v.y - __half2float(h1));
    __half l2 = __float2half_rn(v.z - __half2float(h2));
    __half l3 = __float2half_rn(v.w - __half2float(h3));
    ushort4 hv = make_ushort4(__half_as_ushort(h0), __half_as_ushort(h1),
                              __half_as_ushort(h2), __half_as_ushort(h3));
    ushort4 lv = make_ushort4(__half_as_ushort(l0), __half_as_ushort(l1),
                              __half_as_ushort(l2), __half_as_ushort(l3));
    ((ushort4*)hi)[i] = hv;
    ((ushort4*)lo)[i] = lv;
}

// src [K][ld] fp32 -> dst [N][Kdim] fp16 (transposed, hi only)
__global__ void convertBT_hi(const float* __restrict__ src, int ld, int Kdim,
                             __half* __restrict__ hi)
{
    __shared__ float t[32][33];
    int tx = threadIdx.x, ty = threadIdx.y;
    int k0 = blockIdx.x * 32, n0 = blockIdx.y * 32;
    #pragma unroll
    for (int i = 0; i < 4; i++)
        t[ty + 8 * i][tx] = src[(size_t)(k0 + ty + 8 * i) * ld + n0 + tx];
    __syncthreads();
    #pragma unroll
    for (int i = 0; i < 4; i++) {
        float v = t[tx][ty + 8 * i];
        hi[(size_t)(n0 + ty + 8 * i) * Kdim + k0 + tx] = __float2half_rn(v);
    }
}

// ============= 128x128 HMMA GEMM (2-stage), A split / B hi =================
// buffer: Ahi[0,10240) Alo[10240,20480) Bh[20480,30720)
#define BUFSZ  30720
#define GEMM_SMEM (2*BUFSZ)

__global__ __launch_bounds__(256) void gemm_mma(
    const __half* __restrict__ Ahi, const __half* __restrict__ Alo,
    const __half* __restrict__ Bhi,
    float* __restrict__ C, int K, int N)
{
    extern __shared__ char smc[];
    uint32_t sb = smem_u32(smc);
    int tid = threadIdx.x, lane = tid & 31, wid = tid >> 5;
    int wm = wid >> 2, wn = wid & 3;
    int tile_n = blockIdx.x * 128, tile_m = blockIdx.y * 128;

    int lrow = tid & 127, hf = tid >> 7;
    const uint4* Ag = (const uint4*)((hf ? Alo : Ahi) + (size_t)(tile_m + lrow) * K);
    const uint4* Bg = (const uint4*)(Bhi + (size_t)(tile_n + lrow) * K);
    uint32_t dstA = sb + hf * 10240 + lrow * 80;
    uint32_t dstB = sb + 20480 + lrow * 80;

    float acc[4][4][4];
    #pragma unroll
    for (int i = 0; i < 4; i++)
        #pragma unroll
        for (int j = 0; j < 4; j++)
            #pragma unroll
            for (int e = 0; e < 4; e++) acc[i][j][e] = 0.f;

    int nch = K >> 5;
    #pragma unroll
    for (int p = 0; p < 2; p++) {
        #pragma unroll
        for (int j = 0; j < 4; j++) {
            cpa16(dstA + p * BUFSZ + j * 16, Ag + p * 4 + j);
            if (hf == 0) cpa16(dstB + p * BUFSZ + j * 16, Bg + p * 4 + j);
        }
        CPA_COMMIT();
    }

    for (int c = 0; c < nch; c++) {
        if (c + 1 < nch) { CPA_WAIT1(); } else { CPA_WAIT0(); }
        __syncthreads();

        uint32_t base = sb + (c & 1) * BUFSZ;
        #pragma unroll
        for (int s = 0; s < 2; s++) {
            uint32_t bfr[4][2];
            #pragma unroll
            for (int jp = 0; jp < 2; jp++) {
                uint32_t nloc = (uint32_t)(wn * 32 + jp * 16 + ((lane >> 4) & 1) * 8 + (lane & 7));
                uint32_t off = 20480 + nloc * 80 + s * 32 + ((lane >> 3) & 1) * 16;
                uint32_t t[4];
                ldsm4(t, base + off);
                bfr[jp * 2][0] = t[0]; bfr[jp * 2][1] = t[1];
                bfr[jp * 2 + 1][0] = t[2]; bfr[jp * 2 + 1][1] = t[3];
            }
            #pragma unroll
            for (int i = 0; i < 4; i++) {
                uint32_t ra = (uint32_t)(wm * 64 + i * 16 + (lane & 7) + ((lane >> 3) & 1) * 8) * 80
                            + s * 32 + ((lane >> 4) & 1) * 16;
                uint32_t ah[4], al[4];
                ldsm4(ah, base + ra);
                ldsm4(al, base + 10240 + ra);
                #pragma unroll
                for (int j = 0; j < 4; j++) {
                    mma16816(acc[i][j], ah, bfr[j]);
                    mma16816(acc[i][j], al, bfr[j]);
                }
            }
        }
        __syncthreads();

        if (c + 2 < nch) {
            uint32_t dA = dstA + (c & 1) * BUFSZ;
            uint32_t dB = dstB + (c & 1) * BUFSZ;
            const uint4* a = Ag + (size_t)(c + 2) * 4;
            const uint4* b = Bg + (size_t)(c + 2) * 4;
            #pragma unroll
            for (int j = 0; j < 4; j++) {
                cpa16(dA + j * 16, a + j);
                if (hf == 0) cpa16(dB + j * 16, b + j);
            }
            CPA_COMMIT();
        }
    }

    #pragma unroll
    for (int i = 0; i < 4; i++) {
        int row = tile_m + wm * 64 + i * 16 + (lane >> 2);
        #pragma unroll
        for (int j = 0; j < 4; j++) {
            int loc = wn * 32 + j * 8 + (lane & 3) * 2;
            *(float2*)&C[(size_t)row * N + tile_n + loc] =
                make_float2(acc[i][j][0], acc[i][j][1]);
            *(float2*)&C[(size_t)(row + 8) * N + tile_n + loc] =
                make_float2(acc[i][j][2], acc[i][j][3]);
        }
    }
}

// ===== 256x128 HMMA GEMM, 2-stage cp.async (102.4 KB smem -> 2 CTAs/SM) ====
// stage: Ahi[0,20480) Alo[20480,40960) Bh[40960,51200)
#define STG256   51200
#define GEMM_SMEM256 (2*STG256)      // 102400

__global__ __launch_bounds__(256) void gemm256(
    const __half* __restrict__ Ahi, const __half* __restrict__ Alo,
    const __half* __restrict__ Bhi,
    const float* __restrict__ Add, float* __restrict__ C,
    int K, int N, int ldadd)
{
    extern __shared__ char smc[];
    uint32_t sb = smem_u32(smc);
    int tid = threadIdx.x, lane = tid & 31, wid = tid >> 5;
    int wm = wid >> 1, wn = wid & 1;
    int tile_n = blockIdx.x * 128, tile_m = blockIdx.y * 256;

    const uint4* AgHi = (const uint4*)(Ahi + (size_t)(tile_m + tid) * K);
    const uint4* AgLo = (const uint4*)(Alo + (size_t)(tile_m + tid) * K);
    int brow = tid >> 1, bcol = tid & 1;
    const uint4* Bg = (const uint4*)(Bhi + (size_t)(tile_n + brow) * K) + bcol * 2;
    uint32_t dA0 = sb + (uint32_t)tid * 80;
    uint32_t dA1 = sb + 20480 + (uint32_t)tid * 80;
    uint32_t dB  = sb + 40960 + (uint32_t)brow * 80 + (uint32_t)bcol * 32;

    float acc[4][8][4];
    #pragma unroll
    for (int i = 0; i < 4; i++)
        #pragma unroll
        for (int j = 0; j < 8; j++)
            #pragma unroll
            for (int e = 0; e < 4; e++) acc[i][j][e] = 0.f;

    int nch = K >> 5;
    #pragma unroll
    for (int p = 0; p < 2; p++) {
        uint32_t o = p * STG256;
        #pragma unroll
        for (int j = 0; j < 4; j++) {
            cpa16(dA0 + o + j * 16, AgHi + p * 4 + j);
            cpa16(dA1 + o + j * 16, AgLo + p * 4 + j);
        }
        cpa16(dB + o,      Bg + p * 4);
        cpa16(dB + o + 16, Bg + p * 4 + 1);
        CPA_COMMIT();
    }

    for (int c = 0; c < nch; c++) {
        if (c + 1 < nch) { CPA_WAIT1(); } else { CPA_WAIT0(); }
        __syncthreads();

        uint32_t base = sb + (uint32_t)(c & 1) * STG256;
        #pragma unroll
        for (int s = 0; s < 2; s++) {
            uint32_t ah[4][4], al[4][4];
            #pragma unroll
            for (int i = 0; i < 4; i++) {
                uint32_t ra = (uint32_t)(wm * 64 + i * 16 + (lane & 7) + ((lane >> 3) & 1) * 8) * 80
                            + s * 32 + ((lane >> 4) & 1) * 16;
                ldsm4(ah[i], base + ra);
                ldsm4(al[i], base + 20480 + ra);
            }
            #pragma unroll
            for (int jp = 0; jp < 4; jp++) {
                uint32_t nloc = (uint32_t)(wn * 64 + jp * 16 + ((lane >> 4) & 1) * 8 + (lane & 7));
                uint32_t off = 40960 + nloc * 80 + s * 32 + ((lane >> 3) & 1) * 16;
                uint32_t tb[4];
                ldsm4(tb, base + off);
                #pragma unroll
                for (int i = 0; i < 4; i++) {
                    mma16816(acc[i][jp * 2],     ah[i], tb);
                    mma16816(acc[i][jp * 2],     al[i], tb);
                    mma16816(acc[i][jp * 2 + 1], ah[i], tb + 2);
                    mma16816(acc[i][jp * 2 + 1], al[i], tb + 2);
                }
            }
        }
        __syncthreads();

        if (c + 2 < nch) {
            uint32_t o = (uint32_t)(c & 1) * STG256;
            const uint4* a0 = AgHi + (size_t)(c + 2) * 4;
            const uint4* a1 = AgLo + (size_t)(c + 2) * 4;
            const uint4* b  = Bg   + (size_t)(c + 2) * 4;
            #pragma unroll
            for (int j = 0; j < 4; j++) {
                cpa16(dA0 + o + j * 16, a0 + j);
                cpa16(dA1 + o + j * 16, a1 + j);
            }
            cpa16(dB + o,      b);
            cpa16(dB + o + 16, b + 1);
            CPA_COMMIT();
        }
    }

    int addn = (tile_n >= 4096) ? tile_n - 2048 : tile_n;
    #pragma unroll
    for (int i = 0; i < 4; i++) {
        int row = tile_m + wm * 64 + i * 16 + (lane >> 2);
        #pragma unroll
        for (int j = 0; j < 8; j++) {
            int loc = wn * 64 + j * 8 + (lane & 3) * 2;
            float2 v0 = make_float2(acc[i][j][0], acc[i][j][1]);
            float2 v1 = make_float2(acc[i][j][2], acc[i][j][3]);
            if (Add) {
                float2 a0 = *(const float2*)&Add[(size_t)row * ldadd + addn + loc];
                float2 a1 = *(const float2*)&Add[(size_t)(row + 8) * ldadd + addn + loc];
                v0.x += a0.x; v0.y += a0.y;
                v1.x += a1.x; v1.y += a1.y;
            }
            *(float2*)&C[(size_t)row * N + tile_n + loc] = v0;
            *(float2*)&C[(size_t)(row + 8) * N + tile_n + loc] = v1;
        }
    }
}

// -------- blend + rmsnorm + exact k-th + relu-shift; writes fp16 planes ----
__global__ __launch_bounds__(512) void ts_rowops_kernel(
    const float* __restrict__ last, const float* __restrict__ w,
    const float* __restrict__ ts,
    __half* __restrict__ tsHi, __half* __restrict__ tsLo)
{
    __shared__ float sv[512];
    __shared__ float rbuf[512];
    int row = blockIdx.x;
    int j = threadIdx.x;
    size_t idx = (size_t)row * TS_ + j;

    float x = 0.5f * ts[idx] + 0.5f * last[idx];
    rbuf[j] = x * x;
    __syncthreads();
    #pragma unroll
    for (int s2 = 256; s2 > 0; s2 >>= 1) {
        if (j < s2) rbuf[j] += rbuf[j + s2];
        __syncthreads();
    }
    float var = rbuf[0] * (1.f / 512.f);
    float y = x * rsqrtf(var + 1e-6f) * w[j];
    sv[j] = y;
    __syncthreads();

    for (int k = 2; k <= 512; k <<= 1) {
        for (int jj = k >> 1; jj > 0; jj >>= 1) {
            int ixj = j ^ jj;
            if (ixj > j) {
                float a = sv[j], b = sv[ixj];
                bool asc = ((j & k) == 0);
                if (asc ? (a > b) : (a < b)) { sv[j] = b; sv[ixj] = a; }
            }
            __syncthreads();
        }
    }
    float kth = sv[KIDX - 1];
    split_store(fmaxf(y - kth, 0.f), tsHi, tsLo, idx);
}

// ------- RoPE + transpose to head-major fp16 planes [B,NH,S,HD] -----------
__global__ void rope_transpose_kernel(
    const float* __restrict__ qkv,
    __half* __restrict__ Qhi, __half* __restrict__ Qlo,
    __half* __restrict__ Khi, __half* __restrict__ Vhi)
{
    int i = blockIdx.x * blockDim.x + threadIdx.x;
    if (i >= ROWS * NH_ * 64) return;
    int d = i & 63;
    int h = (i >> 6) & (NH_ - 1);
    int row = i >> 10;
    int b = row >> 11;
    int s = row & (S_ - 1);

    float inv = g_invf[d];
    float ang = (float)s * inv;
    float cs, sn;
    sincosf(ang, &sn, &cs);

    size_t src = (size_t)row * 6144 + h * HD_ + d;
    float q0 = qkv[src],        q1 = qkv[src + 64];
    float k0 = qkv[src + 2048], k1 = qkv[src + 2048 + 64];
    float v0 = qkv[src + 4096], v1 = qkv[src + 4096 + 64];
    size_t dst = ((size_t)(b * NH_ + h) * S_ + s) * HD_ + d;
    split_store(q0 * cs - q1 * sn, Qhi, Qlo, dst);
    split_store(q1 * cs + q0 * sn, Qhi, Qlo, dst + 64);
    Khi[dst]      = __float2half_rn(k0 * cs - k1 * sn);
    Khi[dst + 64] = __float2half_rn(k1 * cs + k0 * sn);
    Vhi[dst]      = __float2half_rn(v0);
    Vhi[dst + 64] = __float2half_rn(v1);
}

// ---------------- flash attention on mma.sync (fp16 split) -----------------
// 128 q-rows/CTA, 8 warps, 64-key tiles. Q split; K,V fp16-rounded.
// qt reversed (heaviest CTAs scheduled first).
#define LDB2  272
#define TQH   0
#define TQL   34816
#define TKH   69632
#define TVH   87040
#define FLASH_SMEM2 104448

__global__ __launch_bounds__(256) void flash_mma(
    const __half* __restrict__ Qhi, const __half* __restrict__ Qlo,
    const __half* __restrict__ Khi, const __half* __restrict__ Vhi,
    __half* __restrict__ Ohi, __half* __restrict__ Olo)
{
    extern __shared__ char sm[];
    uint32_t sb = smem_u32(sm);
    int tid = threadIdx.x, l = tid & 31, w = tid >> 5;
    int qt = (int)gridDim.x - 1 - (int)blockIdx.x;   // heavy tiles first
    int bh = blockIdx.y;
    size_t bhS = (size_t)bh * S_;

    for (int i = tid; i < 4096; i += 256) {
        int plane = i >> 11, row = (i >> 4) & 127, c = i & 15;
        const uint4* src = (const uint4*)((plane ? Qlo : Qhi) + (bhS + (size_t)qt * 128 + row) * HD_);
        *(uint4*)(sm + (plane ? TQL : TQH) + row * LDB2 + c * 16) = src[c];
    }

    float o[16][4];
    #pragma unroll
    for (int t = 0; t < 16; t++)
        #pragma unroll
        for (int e = 0; e < 4; e++) o[t][e] = 0.f;
    float m1 = -INFINITY, m2 = -INFINITY, l1 = 0.f, l2 = 0.f;
    const float scale = 0.08838834764831845f;

    int ktmax = 2 * qt + 1;
    for (int kt = 0; kt <= ktmax; kt++) {
        __syncthreads();
        for (int i = tid; i < 2048; i += 256) {
            int plane = i >> 10, row = (i >> 4) & 63, c = i & 15;
            const __half* bp = plane ? Vhi : Khi;
            const uint4* src = (const uint4*)(bp + (bhS + (size_t)kt * 64 + row) * HD_);
            uint32_t off = plane ? TVH : TKH;
            *(uint4*)(sm + off + row * LDB2 + c * 16) = src[c];
        }
        __syncthreads();

        float s[8][4];
        #pragma unroll
        for (int t = 0; t < 8; t++)
            #pragma unroll
            for (int e = 0; e < 4; e++) s[t][e] = 0.f;

        #pragma unroll
        for (int kk = 0; kk < 8; kk++) {
            uint32_t ah[4], al[4];
            uint32_t ra = sb + TQH + (uint32_t)(w * 16 + (l & 15)) * LDB2
                        + ((l >> 4) & 1) * 16 + kk * 32;
            ldsm4(ah, ra);
            ldsm4(al, ra + (TQL - TQH));
            #pragma unroll
            for (int g = 0; g < 4; g++) {
                uint32_t bhv[4];
                uint32_t rb = sb + TKH
                    + (uint32_t)(16 * g + (l & 7) + ((l >> 4) & 1) * 8) * LDB2
                    + ((l >> 3) & 1) * 16 + kk * 32;
                ldsm4(bhv, rb);
                mma16816(s[2 * g],     ah, bhv);
                mma16816(s[2 * g],     al, bhv);
                mma16816(s[2 * g + 1], ah, bhv + 2);
                mma16816(s[2 * g + 1], al, bhv + 2);
            }
        }

        int r1 = qt * 128 + w * 16 + (l >> 2), r2 = r1 + 8;
        int cb = (kt << 6) + ((l & 3) << 1);
        if (kt >= 2 * qt) {
            #pragma unroll
            for (int t = 0; t < 8; t++) {
                int c0 = cb + t * 8, c1 = c0 + 1;
                s[t][0] = (c0 <= r1) ? s[t][0] * scale : -1e30f;
                s[t][1] = (c1 <= r1) ? s[t][1] * scale : -1e30f;
                s[t][2] = (c0 <= r2) ? s[t][2] * scale : -1e30f;
                s[t][3] = (c1 <= r2) ? s[t][3] * scale : -1e30f;
            }
        } else {
            #pragma unroll
            for (int t = 0; t < 8; t++)
                #pragma unroll
                for (int e = 0; e < 4; e++) s[t][e] *= scale;
        }

        float rm1 = -INFINITY, rm2 = -INFINITY;
        #pragma unroll
        for (int t = 0; t < 8; t++) {
            rm1 = fmaxf(rm1, fmaxf(s[t][0], s[t][1]));
            rm2 = fmaxf(rm2, fmaxf(s[t][2], s[t][3]));
        }
        rm1 = fmaxf(rm1, __shfl_xor_sync(0xffffffffu, rm1, 1));
        rm1 = fmaxf(rm1, __shfl_xor_sync(0xffffffffu, rm1, 2));
        rm2 = fmaxf(rm2, __shfl_xor_sync(0xffffffffu, rm2, 1));
        rm2 = fmaxf(rm2, __shfl_xor_sync(0xffffffffu, rm2, 2));
        float mn1 = fmaxf(m1, rm1), mn2 = fmaxf(m2, rm2);
        float cr1 = __expf(m1 - mn1), cr2 = __expf(m2 - mn2);
        m1 = mn1; m2 = mn2;
        float rs1 = 0.f, rs2 = 0.f;
        #pragma unroll
        for (int t = 0; t < 8; t++) {
            s[t][0] = __expf(s[t][0] - mn1);
            s[t][1] = __expf(s[t][1] - mn1);
            s[t][2] = __expf(s[t][2] - mn2);
            s[t][3] = __expf(s[t][3] - mn2);
            rs1 += s[t][0] + s[t][1];
            rs2 += s[t][2] + s[t][3];
        }
        rs1 += __shfl_xor_sync(0xffffffffu, rs1, 1);
        rs1 += __shfl_xor_sync(0xffffffffu, rs1, 2);
        rs2 += __shfl_xor_sync(0xffffffffu, rs2, 1);
        rs2 += __shfl_xor_sync(0xffffffffu, rs2, 2);
        l1 = l1 * cr1 + rs1;
        l2 = l2 * cr2 + rs2;
        #pragma unroll
        for (int t = 0; t < 16; t++) {
            o[t][0] *= cr1; o[t][1] *= cr1;
            o[t][2] *= cr2; o[t][3] *= cr2;
        }

        // O += P V : P split hi/lo (exact), V fp16
        #pragma unroll
        for (int t = 0; t < 4; t++) {
            uint32_t pah[4], pal[4];
            float* s0 = s[2 * t];
            float* s1 = s[2 * t + 1];
            pah[0] = pack_h2(s0[0], s0[1]);
            pah[1] = pack_h2(s0[2], s0[3]);
            pah[2] = pack_h2(s1[0], s1[1]);
            pah[3] = pack_h2(s1[2], s1[3]);
            float q00 = s0[0] - __half2float(__ushort_as_half((unsigned short)(pah[0] & 0xffff)));
            float q01 = s0[1] - __half2float(__ushort_as_half((unsigned short)(pah[0] >> 16)));
            float q02 = s0[2] - __half2float(__ushort_as_half((unsigned short)(pah[1] & 0xffff)));
            float q03 = s0[3] - __half2float(__ushort_as_half((unsigned short)(pah[1] >> 16)));
            float q10 = s1[0] - __half2float(__ushort_as_half((unsigned short)(pah[2] & 0xffff)));
            float q11 = s1[1] - __half2float(__ushort_as_half((unsigned short)(pah[2] >> 16)));
            float q12 = s1[2] - __half2float(__ushort_as_half((unsigned short)(pah[3] & 0xffff)));
            float q13 = s1[3] - __half2float(__ushort_as_half((unsigned short)(pah[3] >> 16)));
            pal[0] = pack_h2(q00, q01);
            pal[1] = pack_h2(q02, q03);
            pal[2] = pack_h2(q10, q11);
            pal[3] = pack_h2(q12, q13);

            #pragma unroll
            for (int g = 0; g < 8; g++) {
                uint32_t bhv[4];
                uint32_t rb = sb + TVH
                    + (uint32_t)(16 * t + (l & 7) + ((l >> 3) & 1) * 8) * LDB2
                    + 32 * g + ((l >> 4) & 1) * 16;
                ldsm4t(bhv, rb);
                mma16816(o[2 * g],     pah, bhv);
                mma16816(o[2 * g],     pal, bhv);
                mma16816(o[2 * g + 1], pah, bhv + 2);
                mma16816(o[2 * g + 1], pal, bhv + 2);
            }
        }
    }

    float il1 = 1.f / l1, il2 = 1.f / l2;
    int b = bh >> 4, h = bh & (NH_ - 1);
    int sr = qt * 128 + w * 16 + (l >> 2);
    size_t base1 = ((size_t)(b * S_ + sr)) * H_ + h * HD_;
    size_t base2 = base1 + (size_t)8 * H_;
    #pragma unroll
    for (int t = 0; t < 16; t++) {
        int d = t * 8 + (l & 3) * 2;
        float v0 = o[t][0] * il1, v1 = o[t][1] * il1;
        float v2 = o[t][2] * il2, v3 = o[t][3] * il2;
        uint32_t h0 = pack_h2(v0, v1);
        float w0 = v0 - __half2float(__ushort_as_half((unsigned short)(h0 & 0xffff)));
        float w1 = v1 - __half2float(__ushort_as_half((unsigned short)(h0 >> 16)));
        uint32_t h1 = pack_h2(v2, v3);
        float w2 = v2 - __half2float(__ushort_as_half((unsigned short)(h1 & 0xffff)));
        float w3 = v3 - __half2float(__ushort_as_half((unsigned short)(h1 >> 16)));
        *(uint32_t*)&Ohi[base1 + d] = h0;
        *(uint32_t*)&Olo[base1 + d] = pack_h2(w0, w1);
        *(uint32_t*)&Ohi[base2 + d] = h1;
        *(uint32_t*)&Olo[base2 + d] = pack_h2(w2, w3);
    }
}

// ---------------------------------------------------------------------------
extern "C" void kernel_launch(void* const* d_in, const int* in_sizes, int n_in,
                              void* d_out, int out_size)
{
    const float* hidden = (const float*)d_in[0];
    const float* lastts = (const float*)d_in[1];
    const float* Wq     = (const float*)d_in[2];
    const float* Wk     = (const float*)d_in[3];
    const float* Wv     = (const float*)d_in[4];
    const float* Wo     = (const float*)d_in[5];
    const float* Wts    = (const float*)d_in[6];
    const float* tsw    = (const float*)d_in[7];
    const float* Worig  = (const float*)d_in[8];
    float* out = (float*)d_out;

    float *ts, *add, *qkv;
    __half *Ahi, *Alo, *tsHi, *tsLo, *WHi;
    __half *Qhi, *Qlo, *Khi, *Vhi;
    cudaGetSymbolAddress((void**)&ts,   g_ts);
    cudaGetSymbolAddress((void**)&add,  g_add);
    cudaGetSymbolAddress((void**)&qkv,  g_qkv);
    cudaGetSymbolAddress((void**)&Ahi,  g_Ahi);
    cudaGetSymbolAddress((void**)&Alo,  g_Alo);
    cudaGetSymbolAddress((void**)&tsHi, g_tsHi);
    cudaGetSymbolAddress((void**)&tsLo, g_tsLo);
    cudaGetSymbolAddress((void**)&WHi,  g_WHi);
    cudaGetSymbolAddress((void**)&Qhi,  g_Qhi);
    cudaGetSymbolAddress((void**)&Qlo,  g_Qlo);
    cudaGetSymbolAddress((void**)&Khi,  g_Khi);
    cudaGetSymbolAddress((void**)&Vhi,  g_Vhi);

    cudaFuncSetAttribute(gemm_mma, cudaFuncAttributeMaxDynamicSharedMemorySize, GEMM_SMEM);
    cudaFuncSetAttribute(gemm256, cudaFuncAttributeMaxDynamicSharedMemorySize, GEMM_SMEM256);
    cudaFuncSetAttribute(flash_mma, cudaFuncAttributeMaxDynamicSharedMemorySize, FLASH_SMEM2);

    dim3 tb(32, 8);
    convertA_kernel<<<(ROWS * H_ / 4 + 255) / 256, 256>>>(hidden, Ahi, Alo, ROWS * H_ / 4);
    convertBT_hi<<<dim3(64, 16), tb>>>(Wts, 512, 2048, WHi + WOFF_TS);
    gemm_mma<<<dim3(4, 32), 256, GEMM_SMEM>>>(Ahi, Alo, WHi + WOFF_TS, ts, 2048, 512);
    ts_rowops_kernel<<<ROWS, 512>>>(lastts, tsw, ts, tsHi, tsLo);
    convertBT_hi<<<dim3(16, 128), tb>>>(Worig, 6144, 512, WHi + WOFF_OR);
    // origin GEMM: M=4096 N=4096 K=512
    gemm256<<<dim3(32, 16), 256, GEMM_SMEM256>>>(tsHi, tsLo, WHi + WOFF_OR,
                                                 nullptr, add, 512, 4096, 0);
    init_invf_kernel<<<1, 64>>>();
    convertBT_hi<<<dim3(64, 64), tb>>>(Wq, 2048, 2048, WHi + WOFF_Q);
    convertBT_hi<<<dim3(64, 64), tb>>>(Wk, 2048, 2048, WHi + WOFF_K);
    convertBT_hi<<<dim3(64, 64), tb>>>(Wv, 2048, 2048, WHi + WOFF_V);
    // fused QKV GEMM: M=4096 N=6144 K=2048, Add column-wrapped
    gemm256<<<dim3(48, 16), 256, GEMM_SMEM256>>>(Ahi, Alo, WHi + WOFF_Q,
                                                 add, qkv, 2048, 6144, 4096);
    int tot = ROWS * NH_ * 64;
    rope_transpose_kernel<<<(tot + 255) / 256, 256>>>(qkv, Qhi, Qlo, Khi, Vhi);
    flash_mma<<<dim3(S_ / 128, B_ * NH_), 256, FLASH_SMEM2>>>(Qhi, Qlo, Khi, Vhi,
                                                              Ahi, Alo);
    convertBT_hi<<<dim3(64, 64), tb>>>(Wo, 2048, 2048, WHi + WOFF_O);
    gemm256<<<dim3(16, 16), 256, GEMM_SMEM256>>>(Ahi, Alo, WHi + WOFF_O,
                                                 nullptr, out, 2048, 2048, 0);
}

// round 13
// speedup vs baseline: 1.0491x; 1.0491x over previous
#include <cuda_runtime.h>
#include <cuda_fp16.h>
#include <math.h>
#include <stdint.h>

#define B_   2
#define S_   2048
#define H_   2048
#define NH_  16
#define HD_  128
#define TS_  512
#define ROWS (B_*S_)        // 4096
#define KIDX 460

// ------------------------- mma.sync helpers (baseline PTX) -----------------
__device__ __forceinline__ uint32_t smem_u32(const void* p) {
    uint32_t a;
    asm("{ .reg .u64 t; cvta.to.shared.u64 t,%1; cvt.u32.u64 %0,t; }" : "=r"(a) : "l"(p));
    return a;
}
__device__ __forceinline__ void ldsm4(uint32_t* r, uint32_t addr) {
    asm volatile("ldmatrix.sync.aligned.m8n8.x4.shared.b16 {%0,%1,%2,%3},[%4];"
        : "=r"(r[0]), "=r"(r[1]), "=r"(r[2]), "=r"(r[3]) : "r"(addr));
}
__device__ __forceinline__ void ldsm4t(uint32_t* r, uint32_t addr) {
    asm volatile("ldmatrix.sync.aligned.m8n8.x4.trans.shared.b16 {%0,%1,%2,%3},[%4];"
        : "=r"(r[0]), "=r"(r[1]), "=r"(r[2]), "=r"(r[3]) : "r"(addr));
}
__device__ __forceinline__ void mma16816(float* c, const uint32_t* a, const uint32_t* b) {
    asm volatile(
        "mma.sync.aligned.m16n8k16.row.col.f32.f16.f16.f32 "
        "{%0,%1,%2,%3},{%4,%5,%6,%7},{%8,%9},{%0,%1,%2,%3};"
        : "+f"(c[0]), "+f"(c[1]), "+f"(c[2]), "+f"(c[3])
        : "r"(a[0]), "r"(a[1]), "r"(a[2]), "r"(a[3]), "r"(b[0]), "r"(b[1]));
}
__device__ __forceinline__ uint32_t pack_h2(float a, float b) {
    __half ha = __float2half_rn(a), hb = __float2half_rn(b);
    return (uint32_t)__half_as_ushort(ha) | ((uint32_t)__half_as_ushort(hb) << 16);
}
__device__ __forceinline__ void split_store(float v, __half* hi, __half* lo, size_t idx) {
    __half h = __float2half_rn(v);
    hi[idx] = h;
    lo[idx] = __float2half_rn(v - __half2float(h));
}
__device__ __forceinline__ void cpa16(uint32_t dst, const void* src) {
    asm volatile("cp.async.cg.shared.global [%0],[%1],16;" :: "r"(dst), "l"(src));
}
#define CPA_COMMIT() asm volatile("cp.async.commit_group;" ::: "memory")
#define CPA_WAIT1()  asm volatile("cp.async.wait_group 1;" ::: "memory")
#define CPA_WAIT0()  asm volatile("cp.async.wait_group 0;" ::: "memory")

// ---------------- scratch (device globals) ---------------------------------
__device__ float g_ts[(size_t)ROWS * TS_];
__device__ float g_add[(size_t)ROWS * 4096];
__device__ float g_qkv[(size_t)ROWS * 6144];
__device__ float g_invf[64];

__device__ __half g_Ahi[(size_t)ROWS * H_];     // hidden, later attn-out
__device__ __half g_Alo[(size_t)ROWS * H_];
__device__ __half g_tsHi[(size_t)ROWS * TS_];
__device__ __half g_tsLo[(size_t)ROWS * TS_];
__device__ __half g_Qhi[(size_t)ROWS * H_];
__device__ __half g_Qlo[(size_t)ROWS * H_];
__device__ __half g_Khi[(size_t)ROWS * H_];
__device__ __half g_Vhi[(size_t)ROWS * H_];

#define WOFF_Q  ((size_t)0)
#define WOFF_K  ((size_t)4194304)
#define WOFF_V  ((size_t)8388608)
#define WOFF_O  ((size_t)12582912)
#define WOFF_TS ((size_t)16777216)
#define WOFF_OR ((size_t)17825792)
#define WTOTAL  ((size_t)19922944)
__device__ __half g_WHi[WTOTAL];

__global__ void init_invf_kernel() {
    int d = threadIdx.x;
    if (d < 64) g_invf[d] = (float)exp(-(double)d * (9.210340371976184 / 64.0));
}

// ---------------- convert kernels ------------------------------------------
__global__ void convertA_kernel(const float* __restrict__ src,
                                __half* __restrict__ hi,
                                __half* __restrict__ lo, int n4)
{
    int i = blockIdx.x * blockDim.x + threadIdx.x;
    if (i >= n4) return;
    float4 v = ((const float4*)src)[i];
    __half h0 = __float2half_rn(v.x);
    __half h1 = __float2half_rn(v.y);
    __half h2 = __float2half_rn(v.z);
    __half h3 = __float2half_rn(v.w);
    __half l0 = __float2half_rn(v.x - __half2float(h0));
    __half l1 = __float2half_rn(v.y - __half2float(h1));
    __half l2 = __float2half_rn(v.z - __half2float(h2));
    __half l3 = __float2half_rn(v.w - __half2float(h3));
    ushort4 hv = make_ushort4(__half_as_ushort(h0), __half_as_ushort(h1),
                              __half_as_ushort(h2), __half_as_ushort(h3));
    ushort4 lv = make_ushort4(__half_as_ushort(l0), __half_as_ushort(l1),
                              __half_as_ushort(l2), __half_as_ushort(l3));
    ((ushort4*)hi)[i] = hv;
    ((ushort4*)lo)[i] = lv;
}

// src [K][ld] fp32 -> dst [N][Kdim] fp16 (transposed, hi only)
__global__ void convertBT_hi(const float* __restrict__ src, int ld, int Kdim,
                             __half* __restrict__ hi)
{
    __shared__ float t[32][33];
    int tx = threadIdx.x, ty = threadIdx.y;
    int k0 = blockIdx.x * 32, n0 = blockIdx.y * 32;
    #pragma unroll
    for (int i = 0; i < 4; i++)
        t[ty + 8 * i][tx] = src[(size_t)(k0 + ty + 8 * i) * ld + n0 + tx];
    __syncthreads();
    #pragma unroll
    for (int i = 0; i < 4; i++) {
        float v = t[tx][ty + 8 * i];
        hi[(size_t)(n0 + ty + 8 * i) * Kdim + k0 + tx] = __float2half_rn(v);
    }
}

// three 2048x2048 weights -> one contiguous [6144][2048] fp16 transposed
__global__ void convertBT3_hi(const float* __restrict__ W0,
                              const float* __restrict__ W1,
                              const float* __restrict__ W2,
                              __half* __restrict__ hi)
{
    __shared__ float t[32][33];
    const float* src = (blockIdx.z == 0) ? W0 : (blockIdx.z == 1) ? W1 : W2;
    __half* dst = hi + (size_t)blockIdx.z * 4194304;
    int tx = threadIdx.x, ty = threadIdx.y;
    int k0 = blockIdx.x * 32, n0 = blockIdx.y * 32;
    #pragma unroll
    for (int i = 0; i < 4; i++)
        t[ty + 8 * i][tx] = src[(size_t)(k0 + ty + 8 * i) * 2048 + n0 + tx];
    __syncthreads();
    #pragma unroll
    for (int i = 0; i < 4; i++) {
        float v = t[tx][ty + 8 * i];
        dst[(size_t)(n0 + ty + 8 * i) * 2048 + k0 + tx] = __float2half_rn(v);
    }
}

// ============= 128x128 HMMA GEMM (2-stage), A split / B hi =================
#define BUFSZ  30720
#define GEMM_SMEM (2*BUFSZ)

__global__ __launch_bounds__(256) void gemm_mma(
    const __half* __restrict__ Ahi, const __half* __restrict__ Alo,
    const __half* __restrict__ Bhi,
    float* __restrict__ C, int K, int N)
{
    extern __shared__ char smc[];
    uint32_t sb = smem_u32(smc);
    int tid = threadIdx.x, lane = tid & 31, wid = tid >> 5;
    int wm = wid >> 2, wn = wid & 3;
    int tile_n = blockIdx.x * 128, tile_m = blockIdx.y * 128;

    int lrow = tid & 127, hf = tid >> 7;
    const uint4* Ag = (const uint4*)((hf ? Alo : Ahi) + (size_t)(tile_m + lrow) * K);
    const uint4* Bg = (const uint4*)(Bhi + (size_t)(tile_n + lrow) * K);
    uint32_t dstA = sb + hf * 10240 + lrow * 80;
    uint32_t dstB = sb + 20480 + lrow * 80;

    float acc[4][4][4];
    #pragma unroll
    for (int i = 0; i < 4; i++)
        #pragma unroll
        for (int j = 0; j < 4; j++)
            #pragma unroll
            for (int e = 0; e < 4; e++) acc[i][j][e] = 0.f;

    int nch = K >> 5;
    #pragma unroll
    for (int p = 0; p < 2; p++) {
        #pragma unroll
        for (int j = 0; j < 4; j++) {
            cpa16(dstA + p * BUFSZ + j * 16, Ag + p * 4 + j);
            if (hf == 0) cpa16(dstB + p * BUFSZ + j * 16, Bg + p * 4 + j);
        }
        CPA_COMMIT();
    }

    for (int c = 0; c < nch; c++) {
        if (c + 1 < nch) { CPA_WAIT1(); } else { CPA_WAIT0(); }
        __syncthreads();

        uint32_t base = sb + (c & 1) * BUFSZ;
        #pragma unroll
        for (int s = 0; s < 2; s++) {
            uint32_t bfr[4][2];
            #pragma unroll
            for (int jp = 0; jp < 2; jp++) {
                uint32_t nloc = (uint32_t)(wn * 32 + jp * 16 + ((lane >> 4) & 1) * 8 + (lane & 7));
                uint32_t off = 20480 + nloc * 80 + s * 32 + ((lane >> 3) & 1) * 16;
                uint32_t t[4];
                ldsm4(t, base + off);
                bfr[jp * 2][0] = t[0]; bfr[jp * 2][1] = t[1];
                bfr[jp * 2 + 1][0] = t[2]; bfr[jp * 2 + 1][1] = t[3];
            }
            #pragma unroll
            for (int i = 0; i < 4; i++) {
                uint32_t ra = (uint32_t)(wm * 64 + i * 16 + (lane & 7) + ((lane >> 3) & 1) * 8) * 80
                            + s * 32 + ((lane >> 4) & 1) * 16;
                uint32_t ah[4], al[4];
                ldsm4(ah, base + ra);
                ldsm4(al, base + 10240 + ra);
                #pragma unroll
                for (int j = 0; j < 4; j++) {
                    mma16816(acc[i][j], ah, bfr[j]);
                    mma16816(acc[i][j], al, bfr[j]);
                }
            }
        }
        __syncthreads();

        if (c + 2 < nch) {
            uint32_t dA = dstA + (c & 1) * BUFSZ;
            uint32_t dB = dstB + (c & 1) * BUFSZ;
            const uint4* a = Ag + (size_t)(c + 2) * 4;
            const uint4* b = Bg + (size_t)(c + 2) * 4;
            #pragma unroll
            for (int j = 0; j < 4; j++) {
                cpa16(dA + j * 16, a + j);
                if (hf == 0) cpa16(dB + j * 16, b + j);
            }
            CPA_COMMIT();
        }
    }

    #pragma unroll
    for (int i = 0; i < 4; i++) {
        int row = tile_m + wm * 64 + i * 16 + (lane >> 2);
        #pragma unroll
        for (int j = 0; j < 4; j++) {
            int loc = wn * 32 + j * 8 + (lane & 3) * 2;
            *(float2*)&C[(size_t)row * N + tile_n + loc] =
                make_float2(acc[i][j][0], acc[i][j][1]);
            *(float2*)&C[(size_t)(row + 8) * N + tile_n + loc] =
                make_float2(acc[i][j][2], acc[i][j][3]);
        }
    }
}

// ===== 256x128 HMMA GEMM, 2-stage cp.async =====
#define STG256   51200
#define GEMM_SMEM256 (2*STG256)

__global__ __launch_bounds__(256) void gemm256(
    const __half* __restrict__ Ahi, const __half* __restrict__ Alo,
    const __half* __restrict__ Bhi,
    float* __restrict__ C, int K, int N)
{
    extern __shared__ char smc[];
    uint32_t sb = smem_u32(smc);
    int tid = threadIdx.x, lane = tid & 31, wid = tid >> 5;
    int wm = wid >> 1, wn = wid & 1;
    int tile_n = blockIdx.x * 128, tile_m = blockIdx.y * 256;

    const uint4* AgHi = (const uint4*)(Ahi + (size_t)(tile_m + tid) * K);
    const uint4* AgLo = (const uint4*)(Alo + (size_t)(tile_m + tid) * K);
    int brow = tid >> 1, bcol = tid & 1;
    const uint4* Bg = (const uint4*)(Bhi + (size_t)(tile_n + brow) * K) + bcol * 2;
    uint32_t dA0 = sb + (uint32_t)tid * 80;
    uint32_t dA1 = sb + 20480 + (uint32_t)tid * 80;
    uint32_t dB  = sb + 40960 + (uint32_t)brow * 80 + (uint32_t)bcol * 32;

    float acc[4][8][4];
    #pragma unroll
    for (int i = 0; i < 4; i++)
        #pragma unroll
        for (int j = 0; j < 8; j++)
            #pragma unroll
            for (int e = 0; e < 4; e++) acc[i][j][e] = 0.f;

    int nch = K >> 5;
    #pragma unroll
    for (int p = 0; p < 2; p++) {
        uint32_t o = p * STG256;
        #pragma unroll
        for (int j = 0; j < 4; j++) {
            cpa16(dA0 + o + j * 16, AgHi + p * 4 + j);
            cpa16(dA1 + o + j * 16, AgLo + p * 4 + j);
        }
        cpa16(dB + o,      Bg + p * 4);
        cpa16(dB + o + 16, Bg + p * 4 + 1);
        CPA_COMMIT();
    }

    for (int c = 0; c < nch; c++) {
        if (c + 1 < nch) { CPA_WAIT1(); } else { CPA_WAIT0(); }
        __syncthreads();

        uint32_t base = sb + (uint32_t)(c & 1) * STG256;
        #pragma unroll
        for (int s = 0; s < 2; s++) {
            uint32_t ah[4][4], al[4][4];
            #pragma unroll
            for (int i = 0; i < 4; i++) {
                uint32_t ra = (uint32_t)(wm * 64 + i * 16 + (lane & 7) + ((lane >> 3) & 1) * 8) * 80
                            + s * 32 + ((lane >> 4) & 1) * 16;
                ldsm4(ah[i], base + ra);
                ldsm4(al[i], base + 20480 + ra);
            }
            #pragma unroll
            for (int jp = 0; jp < 4; jp++) {
                uint32_t nloc = (uint32_t)(wn * 64 + jp * 16 + ((lane >> 4) & 1) * 8 + (lane & 7));
                uint32_t off = 40960 + nloc * 80 + s * 32 + ((lane >> 3) & 1) * 16;
                uint32_t tb[4];
                ldsm4(tb, base + off);
                #pragma unroll
                for (int i = 0; i < 4; i++) {
                    mma16816(acc[i][jp * 2],     ah[i], tb);
                    mma16816(acc[i][jp * 2],     al[i], tb);
                    mma16816(acc[i][jp * 2 + 1], ah[i], tb + 2);
                    mma16816(acc[i][jp * 2 + 1], al[i], tb + 2);
                }
            }
        }
        __syncthreads();

        if (c + 2 < nch) {
            uint32_t o = (uint32_t)(c & 1) * STG256;
            const uint4* a0 = AgHi + (size_t)(c + 2) * 4;
            const uint4* a1 = AgLo + (size_t)(c + 2) * 4;
            const uint4* b  = Bg   + (size_t)(c + 2) * 4;
            #pragma unroll
            for (int j = 0; j < 4; j++) {
                cpa16(dA0 + o + j * 16, a0 + j);
                cpa16(dA1 + o + j * 16, a1 + j);
            }
            cpa16(dB + o,      b);
            cpa16(dB + o + 16, b + 1);
            CPA_COMMIT();
        }
    }

    #pragma unroll
    for (int i = 0; i < 4; i++) {
        int row = tile_m + wm * 64 + i * 16 + (lane >> 2);
        #pragma unroll
        for (int j = 0; j < 8; j++) {
            int loc = wn * 64 + j * 8 + (lane & 3) * 2;
            *(float2*)&C[(size_t)row * N + tile_n + loc] =
                make_float2(acc[i][j][0], acc[i][j][1]);
            *(float2*)&C[(size_t)(row + 8) * N + tile_n + loc] =
                make_float2(acc[i][j][2], acc[i][j][3]);
        }
    }
}

// -------- blend + rmsnorm + exact k-th + relu-shift; writes fp16 planes ----
__global__ __launch_bounds__(512) void ts_rowops_kernel(
    const float* __restrict__ last, const float* __restrict__ w,
    const float* __restrict__ ts,
    __half* __restrict__ tsHi, __half* __restrict__ tsLo)
{
    __shared__ float sv[512];
    __shared__ float rbuf[512];
    int row = blockIdx.x;
    int j = threadIdx.x;
    size_t idx = (size_t)row * TS_ + j;

    float x = 0.5f * ts[idx] + 0.5f * last[idx];
    rbuf[j] = x * x;
    __syncthreads();
    #pragma unroll
    for (int s2 = 256; s2 > 0; s2 >>= 1) {
        if (j < s2) rbuf[j] += rbuf[j + s2];
        __syncthreads();
    }
    float var = rbuf[0] * (1.f / 512.f);
    float y = x * rsqrtf(var + 1e-6f) * w[j];
    sv[j] = y;
    __syncthreads();

    for (int k = 2; k <= 512; k <<= 1) {
        for (int jj = k >> 1; jj > 0; jj >>= 1) {
            int ixj = j ^ jj;
            if (ixj > j) {
                float a = sv[j], b = sv[ixj];
                bool asc = ((j & k) == 0);
                if (asc ? (a > b) : (a < b)) { sv[j] = b; sv[ixj] = a; }
            }
            __syncthreads();
        }
    }
    float kth = sv[KIDX - 1];
    split_store(fmaxf(y - kth, 0.f), tsHi, tsLo, idx);
}

// ------- RoPE + add + transpose to head-major fp16 planes [B,NH,S,HD] -----
__global__ void rope_transpose_kernel(
    const float* __restrict__ qkv, const float* __restrict__ add,
    __half* __restrict__ Qhi, __half* __restrict__ Qlo,
    __half* __restrict__ Khi, __half* __restrict__ Vhi)
{
    int i = blockIdx.x * blockDim.x + threadIdx.x;
    if (i >= ROWS * NH_ * 64) return;
    int d = i & 63;
    int h = (i >> 6) & (NH_ - 1);
    int row = i >> 10;
    int b = row >> 11;
    int s = row & (S_ - 1);

    float inv = g_invf[d];
    float ang = (float)s * inv;
    float cs, sn;
    sincosf(ang, &sn, &cs);

    size_t src = (size_t)row * 6144 + h * HD_ + d;
    size_t arow = (size_t)row * 4096 + h * HD_ + d;
    float qa0 = add[arow],        qa1 = add[arow + 64];
    float ka0 = add[arow + 2048], ka1 = add[arow + 2048 + 64];
    float q0 = qkv[src] + qa0,           q1 = qkv[src + 64] + qa1;
    float k0 = qkv[src + 2048] + ka0,    k1 = qkv[src + 2048 + 64] + ka1;
    float v0 = qkv[src + 4096] + ka0,    v1 = qkv[src + 4096 + 64] + ka1;
    size_t dst = ((size_t)(b * NH_ + h) * S_ + s) * HD_ + d;
    split_store(q0 * cs - q1 * sn, Qhi, Qlo, dst);
    split_store(q1 * cs + q0 * sn, Qhi, Qlo, dst + 64);
    Khi[dst]      = __float2half_rn(k0 * cs - k1 * sn);
    Khi[dst + 64] = __float2half_rn(k1 * cs + k0 * sn);
    Vhi[dst]      = __float2half_rn(v0);
    Vhi[dst + 64] = __float2half_rn(v1);
}

// ---------------- flash attention, K/V double-buffered via cp.async --------
// 128 q-rows/CTA, 8 warps, 64-key tiles. Q split; K,V fp16.
#define LDB2  272
#define TQH   0
#define TQL   34816
#define KV0   69632
#define VOFF  17408
#define KVSZ  34816
#define FLASH_SMEM2 139264

__global__ __launch_bounds__(256) void flash_mma(
    const __half* __restrict__ Qhi, const __half* __restrict__ Qlo,
    const __half* __restrict__ Khi, const __half* __restrict__ Vhi,
    __half* __restrict__ Ohi, __half* __restrict__ Olo)
{
    extern __shared__ char sm[];
    uint32_t sb = smem_u32(sm);
    int tid = threadIdx.x, l = tid & 31, w = tid >> 5;
    int qt = (int)gridDim.x - 1 - (int)blockIdx.x;   // heavy tiles first
    int bh = blockIdx.y;
    size_t bhS = (size_t)bh * S_;

    for (int i = tid; i < 4096; i += 256) {
        int plane = i >> 11, row = (i >> 4) & 127, c = i & 15;
        const uint4* src = (const uint4*)((plane ? Qlo : Qhi) + (bhS + (size_t)qt * 128 + row) * HD_);
        *(uint4*)(sm + (plane ? TQL : TQH) + row * LDB2 + c * 16) = src[c];
    }
    // prologue: K/V tile 0 -> buffer 0 (async)
    for (int i = tid; i < 2048; i += 256) {
        int plane = i >> 10, row = (i >> 4) & 63, c = i & 15;
        const __half* bp = plane ? Vhi : Khi;
        const uint4* src = (const uint4*)(bp + (bhS + row) * HD_);
        cpa16(sb + KV0 + (plane ? VOFF : 0) + row * LDB2 + c * 16, src + c);
    }
    CPA_COMMIT();

    float o[16][4];
    #pragma unroll
    for (int t = 0; t < 16; t++)
        #pragma unroll
        for (int e = 0; e < 4; e++) o[t][e] = 0.f;
    float m1 = -INFINITY, m2 = -INFINITY, l1 = 0.f, l2 = 0.f;
    const float scale = 0.08838834764831845f;

    int ktmax = 2 * qt + 1;
    for (int kt = 0; kt <= ktmax; kt++) {
        CPA_WAIT0();
        __syncthreads();

        if (kt < ktmax) {
            uint32_t nb = sb + KV0 + (uint32_t)((kt + 1) & 1) * KVSZ;
            for (int i = tid; i < 2048; i += 256) {
                int plane = i >> 10, row = (i >> 4) & 63, c = i & 15;
                const __half* bp = plane ? Vhi : Khi;
                const uint4* src = (const uint4*)(bp + (bhS + (size_t)(kt + 1) * 64 + row) * HD_);
                cpa16(nb + (plane ? VOFF : 0) + row * LDB2 + c * 16, src + c);
            }
            CPA_COMMIT();
        }
        uint32_t kvb = sb + KV0 + (uint32_t)(kt & 1) * KVSZ;

        float s[8][4];
        #pragma unroll
        for (int t = 0; t < 8; t++)
            #pragma unroll
            for (int e = 0; e < 4; e++) s[t][e] = 0.f;

        #pragma unroll
        for (int kk = 0; kk < 8; kk++) {
            uint32_t ah[4], al[4];
            uint32_t ra = sb + TQH + (uint32_t)(w * 16 + (l & 15)) * LDB2
                        + ((l >> 4) & 1) * 16 + kk * 32;
            ldsm4(ah, ra);
            ldsm4(al, ra + (TQL - TQH));
            #pragma unroll
            for (int g = 0; g < 4; g++) {
                uint32_t bhv[4];
                uint32_t rb = kvb
                    + (uint32_t)(16 * g + (l & 7) + ((l >> 4) & 1) * 8) * LDB2
                    + ((l >> 3) & 1) * 16 + kk * 32;
                ldsm4(bhv, rb);
                mma16816(s[2 * g],     ah, bhv);
                mma16816(s[2 * g],     al, bhv);
                mma16816(s[2 * g + 1], ah, bhv + 2);
                mma16816(s[2 * g + 1], al, bhv + 2);
            }
        }

        int r1 = qt * 128 + w * 16 + (l >> 2), r2 = r1 + 8;
        int cb = (kt << 6) + ((l & 3) << 1);
        if (kt >= 2 * qt) {
            #pragma unroll
            for (int t = 0; t < 8; t++) {
                int c0 = cb + t * 8, c1 = c0 + 1;
                s[t][0] = (c0 <= r1) ? s[t][0] * scale : -1e30f;
                s[t][1] = (c1 <= r1) ? s[t][1] * scale : -1e30f;
                s[t][2] = (c0 <= r2) ? s[t][2] * scale : -1e30f;
                s[t][3] = (c1 <= r2) ? s[t][3] * scale : -1e30f;
            }
        } else {
            #pragma unroll
            for (int t = 0; t < 8; t++)
                #pragma unroll
                for (int e = 0; e < 4; e++) s[t][e] *= scale;
        }

        float rm1 = -INFINITY, rm2 = -INFINITY;
        #pragma unroll
        for (int t = 0; t < 8; t++) {
            rm1 = fmaxf(rm1, fmaxf(s[t][0], s[t][1]));
            rm2 = fmaxf(rm2, fmaxf(s[t][2], s[t][3]));
        }
        rm1 = fmaxf(rm1, __shfl_xor_sync(0xffffffffu, rm1, 1));
        rm1 = fmaxf(rm1, __shfl_xor_sync(0xffffffffu, rm1, 2));
        rm2 = fmaxf(rm2, __shfl_xor_sync(0xffffffffu, rm2, 1));
        rm2 = fmaxf(rm2, __shfl_xor_sync(0xffffffffu, rm2, 2));
        float mn1 = fmaxf(m1, rm1), mn2 = fmaxf(m2, rm2);
        float cr1 = __expf(m1 - mn1), cr2 = __expf(m2 - mn2);
        m1 = mn1; m2 = mn2;
        float rs1 = 0.f, rs2 = 0.f;
        #pragma unroll
        for (int t = 0; t < 8; t++) {
            s[t][0] = __expf(s[t][0] - mn1);
            s[t][1] = __expf(s[t][1] - mn1);
            s[t][2] = __expf(s[t][2] - mn2);
            s[t][3] = __expf(s[t][3] - mn2);
            rs1 += s[t][0] + s[t][1];
            rs2 += s[t][2] + s[t][3];
        }
        rs1 += __shfl_xor_sync(0xffffffffu, rs1, 1);
        rs1 += __shfl_xor_sync(0xffffffffu, rs1, 2);
        rs2 += __shfl_xor_sync(0xffffffffu, rs2, 1);
        rs2 += __shfl_xor_sync(0xffffffffu, rs2, 2);
        l1 = l1 * cr1 + rs1;
        l2 = l2 * cr2 + rs2;
        #pragma unroll
        for (int t = 0; t < 16; t++) {
            o[t][0] *= cr1; o[t][1] *= cr1;
            o[t][2] *= cr2; o[t][3] *= cr2;
        }

        // O += P V : P split hi/lo (exact), V fp16
        #pragma unroll
        for (int t = 0; t < 4; t++) {
            uint32_t pah[4], pal[4];
            float* s0 = s[2 * t];
            float* s1 = s[2 * t + 1];
            pah[0] = pack_h2(s0[0], s0[1]);
            pah[1] = pack_h2(s0[2], s0[3]);
            pah[2] = pack_h2(s1[0], s1[1]);
            pah[3] = pack_h2(s1[2], s1[3]);
            float q00 = s0[0] - __half2float(__ushort_as_half((unsigned short)(pah[0] & 0xffff)));
            float q01 = s0[1] - __half2float(__ushort_as_half((unsigned short)(pah[0] >> 16)));
            float q02 = s0[2] - __half2float(__ushort_as_half((unsigned short)(pah[1] & 0xffff)));
            float q03 = s0[3] - __half2float(__ushort_as_half((unsigned short)(pah[1] >> 16)));
            float q10 = s1[0] - __half2float(__ushort_as_half((unsigned short)(pah[2] & 0xffff)));
            float q11 = s1[1] - __half2float(__ushort_as_half((unsigned short)(pah[2] >> 16)));
            float q12 = s1[2] - __half2float(__ushort_as_half((unsigned short)(pah[3] & 0xffff)));
            float q13 = s1[3] - __half2float(__ushort_as_half((unsigned short)(pah[3] >> 16)));
            pal[0] = pack_h2(q00, q01);
            pal[1] = pack_h2(q02, q03);
            pal[2] = pack_h2(q10, q11);
            pal[3] = pack_h2(q12, q13);

            #pragma unroll
            for (int g = 0; g < 8; g++) {
                uint32_t bhv[4];
                uint32_t rb = kvb + VOFF
                    + (uint32_t)(16 * t + (l & 7) + ((l >> 3) & 1) * 8) * LDB2
                    + 32 * g + ((l >> 4) & 1) * 16;
                ldsm4t(bhv, rb);
                mma16816(o[2 * g],     pah, bhv);
                mma16816(o[2 * g],     pal, bhv);
                mma16816(o[2 * g + 1], pah, bhv + 2);
                mma16816(o[2 * g + 1], pal, bhv + 2);
            }
        }
    }

    float il1 = 1.f / l1, il2 = 1.f / l2;
    int b = bh >> 4, h = bh & (NH_ - 1);
    int sr = qt * 128 + w * 16 + (l >> 2);
    size_t base1 = ((size_t)(b * S_ + sr)) * H_ + h * HD_;
    size_t base2 = base1 + (size_t)8 * H_;
    #pragma unroll
    for (int t = 0; t < 16; t++) {
        int d = t * 8 + (l & 3) * 2;
        float v0 = o[t][0] * il1, v1 = o[t][1] * il1;
        float v2 = o[t][2] * il2, v3 = o[t][3] * il2;
        uint32_t h0 = pack_h2(v0, v1);
        float w0 = v0 - __half2float(__ushort_as_half((unsigned short)(h0 & 0xffff)));
        float w1 = v1 - __half2float(__ushort_as_half((unsigned short)(h0 >> 16)));
        uint32_t h1 = pack_h2(v2, v3);
        float w2 = v2 - __half2float(__ushort_as_half((unsigned short)(h1 & 0xffff)));
        float w3 = v3 - __half2float(__ushort_as_half((unsigned short)(h1 >> 16)));
        *(uint32_t*)&Ohi[base1 + d] = h0;
        *(uint32_t*)&Olo[base1 + d] = pack_h2(w0, w1);
        *(uint32_t*)&Ohi[base2 + d] = h1;
        *(uint32_t*)&Olo[base2 + d] = pack_h2(w2, w3);
    }
}

// ---------------------------------------------------------------------------
extern "C" void kernel_launch(void* const* d_in, const int* in_sizes, int n_in,
                              void* d_out, int out_size)
{
    const float* hidden = (const float*)d_in[0];
    const float* lastts = (const float*)d_in[1];
    const float* Wq     = (const float*)d_in[2];
    const float* Wk     = (const float*)d_in[3];
    const float* Wv     = (const float*)d_in[4];
    const float* Wo     = (const float*)d_in[5];
    const float* Wts    = (const float*)d_in[6];
    const float* tsw    = (const float*)d_in[7];
    const float* Worig  = (const float*)d_in[8];
    float* out = (float*)d_out;

    float *ts, *add, *qkv;
    __half *Ahi, *Alo, *tsHi, *tsLo, *WHi;
    __half *Qhi, *Qlo, *Khi, *Vhi;
    cudaGetSymbolAddress((void**)&ts,   g_ts);
    cudaGetSymbolAddress((void**)&add,  g_add);
    cudaGetSymbolAddress((void**)&qkv,  g_qkv);
    cudaGetSymbolAddress((void**)&Ahi,  g_Ahi);
    cudaGetSymbolAddress((void**)&Alo,  g_Alo);
    cudaGetSymbolAddress((void**)&tsHi, g_tsHi);
    cudaGetSymbolAddress((void**)&tsLo, g_tsLo);
    cudaGetSymbolAddress((void**)&WHi,  g_WHi);
    cudaGetSymbolAddress((void**)&Qhi,  g_Qhi);
    cudaGetSymbolAddress((void**)&Qlo,  g_Qlo);
    cudaGetSymbolAddress((void**)&Khi,  g_Khi);
    cudaGetSymbolAddress((void**)&Vhi,  g_Vhi);

    cudaFuncSetAttribute(gemm_mma, cudaFuncAttributeMaxDynamicSharedMemorySize, GEMM_SMEM);
    cudaFuncSetAttribute(gemm256, cudaFuncAttributeMaxDynamicSharedMemorySize, GEMM_SMEM256);
    cudaFuncSetAttribute(flash_mma, cudaFuncAttributeMaxDynamicSharedMemorySize, FLASH_SMEM2);

    dim3 tb(32, 8);
    // #0: hidden -> A planes
    convertA_kernel<<<(ROWS * H_ / 4 + 255) / 256, 256>>>(hidden, Ahi, Alo, ROWS * H_ / 4);
    // #1: Wq|Wk|Wv -> contiguous transposed fp16
    convertBT3_hi<<<dim3(64, 64, 3), tb>>>(Wq, Wk, Wv, WHi + WOFF_Q);
    // #2: rope tables
    init_invf_kernel<<<1, 64>>>();
    // #3 (profiled): fused QKV GEMM M=4096 N=6144 K=2048 (no Add)
    gemm256<<<dim3(48, 16), 256, GEMM_SMEM256>>>(Ahi, Alo, WHi + WOFF_Q, qkv, 2048, 6144);
    // #4..: ts pipeline
    convertBT_hi<<<dim3(64, 16), tb>>>(Wts, 512, 2048, WHi + WOFF_TS);
    gemm_mma<<<dim3(4, 32), 256, GEMM_SMEM>>>(Ahi, Alo, WHi + WOFF_TS, ts, 2048, 512);
    ts_rowops_kernel<<<ROWS, 512>>>(lastts, tsw, ts, tsHi, tsLo);
    convertBT_hi<<<dim3(16, 128), tb>>>(Worig, 6144, 512, WHi + WOFF_OR);
    gemm256<<<dim3(32, 16), 256, GEMM_SMEM256>>>(tsHi, tsLo, WHi + WOFF_OR, add, 512, 4096);
    // RoPE (+add) + transpose
    int tot = ROWS * NH_ * 64;
    rope_transpose_kernel<<<(tot + 255) / 256, 256>>>(qkv, add, Qhi, Qlo, Khi, Vhi);
    // flash attention (double-buffered K/V)
    flash_mma<<<dim3(S_ / 128, B_ * NH_), 256, FLASH_SMEM2>>>(Qhi, Qlo, Khi, Vhi,
                                                              Ahi, Alo);
    // output projection
    convertBT_hi<<<dim3(64, 64), tb>>>(Wo, 2048, 2048, WHi + WOFF_O);
    gemm256<<<dim3(16, 16), 256, GEMM_SMEM256>>>(Ahi, Alo, WHi + WOFF_O, out, 2048, 2048);
}

// round 14
// speedup vs baseline: 1.1905x; 1.1348x over previous
#include <cuda_runtime.h>
#include <cuda_fp16.h>
#include <math.h>
#include <stdint.h>

#define B_   2
#define S_   2048
#define H_   2048
#define NH_  16
#define HD_  128
#define TS_  512
#define ROWS (B_*S_)        // 4096
#define KIDX 460

// ------------------------- mma.sync helpers (baseline PTX) -----------------
__device__ __forceinline__ uint32_t smem_u32(const void* p) {
    uint32_t a;
    asm("{ .reg .u64 t; cvta.to.shared.u64 t,%1; cvt.u32.u64 %0,t; }" : "=r"(a) : "l"(p));
    return a;
}
__device__ __forceinline__ void ldsm4(uint32_t* r, uint32_t addr) {
    asm volatile("ldmatrix.sync.aligned.m8n8.x4.shared.b16 {%0,%1,%2,%3},[%4];"
        : "=r"(r[0]), "=r"(r[1]), "=r"(r[2]), "=r"(r[3]) : "r"(addr));
}
__device__ __forceinline__ void ldsm4t(uint32_t* r, uint32_t addr) {
    asm volatile("ldmatrix.sync.aligned.m8n8.x4.trans.shared.b16 {%0,%1,%2,%3},[%4];"
        : "=r"(r[0]), "=r"(r[1]), "=r"(r[2]), "=r"(r[3]) : "r"(addr));
}
__device__ __forceinline__ void mma16816(float* c, const uint32_t* a, const uint32_t* b) {
    asm volatile(
        "mma.sync.aligned.m16n8k16.row.col.f32.f16.f16.f32 "
        "{%0,%1,%2,%3},{%4,%5,%6,%7},{%8,%9},{%0,%1,%2,%3};"
        : "+f"(c[0]), "+f"(c[1]), "+f"(c[2]), "+f"(c[3])
        : "r"(a[0]), "r"(a[1]), "r"(a[2]), "r"(a[3]), "r"(b[0]), "r"(b[1]));
}
__device__ __forceinline__ uint32_t pack_h2(float a, float b) {
    __half ha = __float2half_rn(a), hb = __float2half_rn(b);
    return (uint32_t)__half_as_ushort(ha) | ((uint32_t)__half_as_ushort(hb) << 16);
}
__device__ __forceinline__ void split_store(float v, __half* hi, __half* lo, size_t idx) {
    __half h = __float2half_rn(v);
    hi[idx] = h;
    lo[idx] = __float2half_rn(v - __half2float(h));
}
__device__ __forceinline__ void cpa16(uint32_t dst, const void* src) {
    asm volatile("cp.async.cg.shared.global [%0],[%1],16;" :: "r"(dst), "l"(src));
}
#define CPA_COMMIT() asm volatile("cp.async.commit_group;" ::: "memory")
#define CPA_WAIT1()  asm volatile("cp.async.wait_group 1;" ::: "memory")
#define CPA_WAIT0()  asm volatile("cp.async.wait_group 0;" ::: "memory")

// ---------------- scratch (device globals) ---------------------------------
__device__ float g_ts[(size_t)ROWS * TS_];
__device__ float g_add[(size_t)ROWS * 4096];
__device__ float g_qkv[(size_t)ROWS * 6144];
__device__ float g_invf[64];

__device__ __half g_Ahi[(size_t)ROWS * H_];     // hidden, later attn-out
__device__ __half g_Alo[(size_t)ROWS * H_];
__device__ __half g_tsHi[(size_t)ROWS * TS_];
__device__ __half g_tsLo[(size_t)ROWS * TS_];
__device__ __half g_Qhi[(size_t)ROWS * H_];
__device__ __half g_Qlo[(size_t)ROWS * H_];
__device__ __half g_Khi[(size_t)ROWS * H_];
__device__ __half g_Vhi[(size_t)ROWS * H_];

#define WOFF_Q  ((size_t)0)
#define WOFF_K  ((size_t)4194304)
#define WOFF_V  ((size_t)8388608)
#define WOFF_O  ((size_t)12582912)
#define WOFF_TS ((size_t)16777216)
#define WOFF_OR ((size_t)17825792)
#define WTOTAL  ((size_t)19922944)
__device__ __half g_WHi[WTOTAL];

__global__ void init_invf_kernel() {
    int d = threadIdx.x;
    if (d < 64) g_invf[d] = (float)exp(-(double)d * (9.210340371976184 / 64.0));
}

// ---------------- convert kernels ------------------------------------------
__global__ void convertA_kernel(const float* __restrict__ src,
                                __half* __restrict__ hi,
                                __half* __restrict__ lo, int n4)
{
    int i = blockIdx.x * blockDim.x + threadIdx.x;
    if (i >= n4) return;
    float4 v = ((const float4*)src)[i];
    __half h0 = __float2half_rn(v.x);
    __half h1 = __float2half_rn(v.y);
    __half h2 = __float2half_rn(v.z);
    __half h3 = __float2half_rn(v.w);
    __half l0 = __float2half_rn(v.x - __half2float(h0));
    __half l1 = __float2half_rn(v.y - __half2float(h1));
    __half l2 = __float2half_rn(v.z - __half2float(h2));
    __half l3 = __float2half_rn(v.w - __half2float(h3));
    ushort4 hv = make_ushort4(__half_as_ushort(h0), __half_as_ushort(h1),
                              __half_as_ushort(h2), __half_as_ushort(h3));
    ushort4 lv = make_ushort4(__half_as_ushort(l0), __half_as_ushort(l1),
                              __half_as_ushort(l2), __half_as_ushort(l3));
    ((ushort4*)hi)[i] = hv;
    ((ushort4*)lo)[i] = lv;
}

// src [K][ld] fp32 -> dst [N][Kdim] fp16 (transposed, hi only)
__global__ void convertBT_hi(const float* __restrict__ src, int ld, int Kdim,
                             __half* __restrict__ hi)
{
    __shared__ float t[32][33];
    int tx = threadIdx.x, ty = threadIdx.y;
    int k0 = blockIdx.x * 32, n0 = blockIdx.y * 32;
    #pragma unroll
    for (int i = 0; i < 4; i++)
        t[ty + 8 * i][tx] = src[(size_t)(k0 + ty + 8 * i) * ld + n0 + tx];
    __syncthreads();
    #pragma unroll
    for (int i = 0; i < 4; i++) {
        float v = t[tx][ty + 8 * i];
        hi[(size_t)(n0 + ty + 8 * i) * Kdim + k0 + tx] = __float2half_rn(v);
    }
}

// three 2048x2048 weights -> one contiguous [6144][2048] fp16 transposed
__global__ void convertBT3_hi(const float* __restrict__ W0,
                              const float* __restrict__ W1,
                              const float* __restrict__ W2,
                              __half* __restrict__ hi)
{
    __shared__ float t[32][33];
    const float* src = (blockIdx.z == 0) ? W0 : (blockIdx.z == 1) ? W1 : W2;
    __half* dst = hi + (size_t)blockIdx.z * 4194304;
    int tx = threadIdx.x, ty = threadIdx.y;
    int k0 = blockIdx.x * 32, n0 = blockIdx.y * 32;
    #pragma unroll
    for (int i = 0; i < 4; i++)
        t[ty + 8 * i][tx] = src[(size_t)(k0 + ty + 8 * i) * 2048 + n0 + tx];
    __syncthreads();
    #pragma unroll
    for (int i = 0; i < 4; i++) {
        float v = t[tx][ty + 8 * i];
        dst[(size_t)(n0 + ty + 8 * i) * 2048 + k0 + tx] = __float2half_rn(v);
    }
}

// ============= 128x128 HMMA GEMM (2-stage), A split / B hi =================
#define BUFSZ  30720
#define GEMM_SMEM (2*BUFSZ)

__global__ __launch_bounds__(256) void gemm_mma(
    const __half* __restrict__ Ahi, const __half* __restrict__ Alo,
    const __half* __restrict__ Bhi,
    float* __restrict__ C, int K, int N)
{
    extern __shared__ char smc[];
    uint32_t sb = smem_u32(smc);
    int tid = threadIdx.x, lane = tid & 31, wid = tid >> 5;
    int wm = wid >> 2, wn = wid & 3;
    int tile_n = blockIdx.x * 128, tile_m = blockIdx.y * 128;

    int lrow = tid & 127, hf = tid >> 7;
    const uint4* Ag = (const uint4*)((hf ? Alo : Ahi) + (size_t)(tile_m + lrow) * K);
    const uint4* Bg = (const uint4*)(Bhi + (size_t)(tile_n + lrow) * K);
    uint32_t dstA = sb + hf * 10240 + lrow * 80;
    uint32_t dstB = sb + 20480 + lrow * 80;

    float acc[4][4][4];
    #pragma unroll
    for (int i = 0; i < 4; i++)
        #pragma unroll
        for (int j = 0; j < 4; j++)
            #pragma unroll
            for (int e = 0; e < 4; e++) acc[i][j][e] = 0.f;

    int nch = K >> 5;
    #pragma unroll
    for (int p = 0; p < 2; p++) {
        #pragma unroll
        for (int j = 0; j < 4; j++) {
            cpa16(dstA + p * BUFSZ + j * 16, Ag + p * 4 + j);
            if (hf == 0) cpa16(dstB + p * BUFSZ + j * 16, Bg + p * 4 + j);
        }
        CPA_COMMIT();
    }

    for (int c = 0; c < nch; c++) {
        if (c + 1 < nch) { CPA_WAIT1(); } else { CPA_WAIT0(); }
        __syncthreads();

        uint32_t base = sb + (c & 1) * BUFSZ;
        #pragma unroll
        for (int s = 0; s < 2; s++) {
            uint32_t bfr[4][2];
            #pragma unroll
            for (int jp = 0; jp < 2; jp++) {
                uint32_t nloc = (uint32_t)(wn * 32 + jp * 16 + ((lane >> 4) & 1) * 8 + (lane & 7));
                uint32_t off = 20480 + nloc * 80 + s * 32 + ((lane >> 3) & 1) * 16;
                uint32_t t[4];
                ldsm4(t, base + off);
                bfr[jp * 2][0] = t[0]; bfr[jp * 2][1] = t[1];
                bfr[jp * 2 + 1][0] = t[2]; bfr[jp * 2 + 1][1] = t[3];
            }
            #pragma unroll
            for (int i = 0; i < 4; i++) {
                uint32_t ra = (uint32_t)(wm * 64 + i * 16 + (lane & 7) + ((lane >> 3) & 1) * 8) * 80
                            + s * 32 + ((lane >> 4) & 1) * 16;
                uint32_t ah[4], al[4];
                ldsm4(ah, base + ra);
                ldsm4(al, base + 10240 + ra);
                #pragma unroll
                for (int j = 0; j < 4; j++) {
                    mma16816(acc[i][j], ah, bfr[j]);
                    mma16816(acc[i][j], al, bfr[j]);
                }
            }
        }
        __syncthreads();

        if (c + 2 < nch) {
            uint32_t dA = dstA + (c & 1) * BUFSZ;
            uint32_t dB = dstB + (c & 1) * BUFSZ;
            const uint4* a = Ag + (size_t)(c + 2) * 4;
            const uint4* b = Bg + (size_t)(c + 2) * 4;
            #pragma unroll
            for (int j = 0; j < 4; j++) {
                cpa16(dA + j * 16, a + j);
                if (hf == 0) cpa16(dB + j * 16, b + j);
            }
            CPA_COMMIT();
        }
    }

    #pragma unroll
    for (int i = 0; i < 4; i++) {
        int row = tile_m + wm * 64 + i * 16 + (lane >> 2);
        #pragma unroll
        for (int j = 0; j < 4; j++) {
            int loc = wn * 32 + j * 8 + (lane & 3) * 2;
            *(float2*)&C[(size_t)row * N + tile_n + loc] =
                make_float2(acc[i][j][0], acc[i][j][1]);
            *(float2*)&C[(size_t)(row + 8) * N + tile_n + loc] =
                make_float2(acc[i][j][2], acc[i][j][3]);
        }
    }
}

// ===== 256x128 HMMA GEMM, 2-stage cp.async, 512 threads / 16 warps =========
// stage: Ahi[0,20480) Alo[20480,40960) Bh[40960,51200)
#define STG256   51200
#define GEMM_SMEM256 (2*STG256)

__global__ __launch_bounds__(512) void gemm256(
    const __half* __restrict__ Ahi, const __half* __restrict__ Alo,
    const __half* __restrict__ Bhi,
    float* __restrict__ C, int K, int N)
{
    extern __shared__ char smc[];
    uint32_t sb = smem_u32(smc);
    int tid = threadIdx.x, lane = tid & 31, wid = tid >> 5;
    int wm = wid >> 2, wn = wid & 3;        // 4x4 warps, warp tile 64x32
    int tile_n = blockIdx.x * 128, tile_m = blockIdx.y * 256;

    // loaders: A rows tid>>1 (2 uint4 each plane), B rows tid>>2 (1 uint4)
    int arow = tid >> 1, aj = (tid & 1) * 2;
    const uint4* AgHi = (const uint4*)(Ahi + (size_t)(tile_m + arow) * K) + aj;
    const uint4* AgLo = (const uint4*)(Alo + (size_t)(tile_m + arow) * K) + aj;
    int brow = tid >> 2, bj = tid & 3;
    const uint4* Bg = (const uint4*)(Bhi + (size_t)(tile_n + brow) * K) + bj;
    uint32_t dA0 = sb + (uint32_t)arow * 80 + aj * 16;
    uint32_t dA1 = sb + 20480 + (uint32_t)arow * 80 + aj * 16;
    uint32_t dB  = sb + 40960 + (uint32_t)brow * 80 + bj * 16;

    float acc[4][4][4];
    #pragma unroll
    for (int i = 0; i < 4; i++)
        #pragma unroll
        for (int j = 0; j < 4; j++)
            #pragma unroll
            for (int e = 0; e < 4; e++) acc[i][j][e] = 0.f;

    int nch = K >> 5;
    #pragma unroll
    for (int p = 0; p < 2; p++) {
        uint32_t o = p * STG256;
        cpa16(dA0 + o,      AgHi + p * 4);
        cpa16(dA0 + o + 16, AgHi + p * 4 + 1);
        cpa16(dA1 + o,      AgLo + p * 4);
        cpa16(dA1 + o + 16, AgLo + p * 4 + 1);
        cpa16(dB + o,       Bg + p * 4);
        CPA_COMMIT();
    }

    for (int c = 0; c < nch; c++) {
        if (c + 1 < nch) { CPA_WAIT1(); } else { CPA_WAIT0(); }
        __syncthreads();

        uint32_t base = sb + (uint32_t)(c & 1) * STG256;
        #pragma unroll
        for (int s = 0; s < 2; s++) {
            uint32_t ah[4][4], al[4][4];
            #pragma unroll
            for (int i = 0; i < 4; i++) {
                uint32_t ra = (uint32_t)(wm * 64 + i * 16 + (lane & 7) + ((lane >> 3) & 1) * 8) * 80
                            + s * 32 + ((lane >> 4) & 1) * 16;
                ldsm4(ah[i], base + ra);
                ldsm4(al[i], base + 20480 + ra);
            }
            #pragma unroll
            for (int jp = 0; jp < 2; jp++) {
                uint32_t nloc = (uint32_t)(wn * 32 + jp * 16 + ((lane >> 4) & 1) * 8 + (lane & 7));
                uint32_t off = 40960 + nloc * 80 + s * 32 + ((lane >> 3) & 1) * 16;
                uint32_t tb[4];
                ldsm4(tb, base + off);
                #pragma unroll
                for (int i = 0; i < 4; i++) {
                    mma16816(acc[i][jp * 2],     ah[i], tb);
                    mma16816(acc[i][jp * 2],     al[i], tb);
                    mma16816(acc[i][jp * 2 + 1], ah[i], tb + 2);
                    mma16816(acc[i][jp * 2 + 1], al[i], tb + 2);
                }
            }
        }
        __syncthreads();

        if (c + 2 < nch) {
            uint32_t o = (uint32_t)(c & 1) * STG256;
            const uint4* a0 = AgHi + (size_t)(c + 2) * 4;
            const uint4* a1 = AgLo + (size_t)(c + 2) * 4;
            const uint4* b  = Bg   + (size_t)(c + 2) * 4;
            cpa16(dA0 + o,      a0);
            cpa16(dA0 + o + 16, a0 + 1);
            cpa16(dA1 + o,      a1);
            cpa16(dA1 + o + 16, a1 + 1);
            cpa16(dB + o,       b);
            CPA_COMMIT();
        }
    }

    #pragma unroll
    for (int i = 0; i < 4; i++) {
        int row = tile_m + wm * 64 + i * 16 + (lane >> 2);
        #pragma unroll
        for (int j = 0; j < 4; j++) {
            int loc = wn * 32 + j * 8 + (lane & 3) * 2;
            *(float2*)&C[(size_t)row * N + tile_n + loc] =
                make_float2(acc[i][j][0], acc[i][j][1]);
            *(float2*)&C[(size_t)(row + 8) * N + tile_n + loc] =
                make_float2(acc[i][j][2], acc[i][j][3]);
        }
    }
}

// -------- blend + rmsnorm + exact k-th + relu-shift; writes fp16 planes ----
__global__ __launch_bounds__(512) void ts_rowops_kernel(
    const float* __restrict__ last, const float* __restrict__ w,
    const float* __restrict__ ts,
    __half* __restrict__ tsHi, __half* __restrict__ tsLo)
{
    __shared__ float sv[512];
    __shared__ float rbuf[512];
    int row = blockIdx.x;
    int j = threadIdx.x;
    size_t idx = (size_t)row * TS_ + j;

    float x = 0.5f * ts[idx] + 0.5f * last[idx];
    rbuf[j] = x * x;
    __syncthreads();
    #pragma unroll
    for (int s2 = 256; s2 > 0; s2 >>= 1) {
        if (j < s2) rbuf[j] += rbuf[j + s2];
        __syncthreads();
    }
    float var = rbuf[0] * (1.f / 512.f);
    float y = x * rsqrtf(var + 1e-6f) * w[j];
    sv[j] = y;
    __syncthreads();

    for (int k = 2; k <= 512; k <<= 1) {
        for (int jj = k >> 1; jj > 0; jj >>= 1) {
            int ixj = j ^ jj;
            if (ixj > j) {
                float a = sv[j], b = sv[ixj];
                bool asc = ((j & k) == 0);
                if (asc ? (a > b) : (a < b)) { sv[j] = b; sv[ixj] = a; }
            }
            __syncthreads();
        }
    }
    float kth = sv[KIDX - 1];
    split_store(fmaxf(y - kth, 0.f), tsHi, tsLo, idx);
}

// ------- RoPE + add + transpose to head-major fp16 planes [B,NH,S,HD] -----
__global__ void rope_transpose_kernel(
    const float* __restrict__ qkv, const float* __restrict__ add,
    __half* __restrict__ Qhi, __half* __restrict__ Qlo,
    __half* __restrict__ Khi, __half* __restrict__ Vhi)
{
    int i = blockIdx.x * blockDim.x + threadIdx.x;
    if (i >= ROWS * NH_ * 64) return;
    int d = i & 63;
    int h = (i >> 6) & (NH_ - 1);
    int row = i >> 10;
    int b = row >> 11;
    int s = row & (S_ - 1);

    float inv = g_invf[d];
    float ang = (float)s * inv;
    float cs, sn;
    sincosf(ang, &sn, &cs);

    size_t src = (size_t)row * 6144 + h * HD_ + d;
    size_t arow = (size_t)row * 4096 + h * HD_ + d;
    float qa0 = add[arow],        qa1 = add[arow + 64];
    float ka0 = add[arow + 2048], ka1 = add[arow + 2048 + 64];
    float q0 = qkv[src] + qa0,           q1 = qkv[src + 64] + qa1;
    float k0 = qkv[src + 2048] + ka0,    k1 = qkv[src + 2048 + 64] + ka1;
    float v0 = qkv[src + 4096] + ka0,    v1 = qkv[src + 4096 + 64] + ka1;
    size_t dst = ((size_t)(b * NH_ + h) * S_ + s) * HD_ + d;
    split_store(q0 * cs - q1 * sn, Qhi, Qlo, dst);
    split_store(q1 * cs + q0 * sn, Qhi, Qlo, dst + 64);
    Khi[dst]      = __float2half_rn(k0 * cs - k1 * sn);
    Khi[dst + 64] = __float2half_rn(k1 * cs + k0 * sn);
    Vhi[dst]      = __float2half_rn(v0);
    Vhi[dst + 64] = __float2half_rn(v1);
}

// ---------------- flash attention, K/V double-buffered via cp.async --------
#define LDB2  272
#define TQH   0
#define TQL   34816
#define KV0   69632
#define VOFF  17408
#define KVSZ  34816
#define FLASH_SMEM2 139264

__global__ __launch_bounds__(256) void flash_mma(
    const __half* __restrict__ Qhi, const __half* __restrict__ Qlo,
    const __half* __restrict__ Khi, const __half* __restrict__ Vhi,
    __half* __restrict__ Ohi, __half* __restrict__ Olo)
{
    extern __shared__ char sm[];
    uint32_t sb = smem_u32(sm);
    int tid = threadIdx.x, l = tid & 31, w = tid >> 5;
    int qt = (int)gridDim.x - 1 - (int)blockIdx.x;
    int bh = blockIdx.y;
    size_t bhS = (size_t)bh * S_;

    for (int i = tid; i < 4096; i += 256) {
        int plane = i >> 11, row = (i >> 4) & 127, c = i & 15;
        const uint4* src = (const uint4*)((plane ? Qlo : Qhi) + (bhS + (size_t)qt * 128 + row) * HD_);
        *(uint4*)(sm + (plane ? TQL : TQH) + row * LDB2 + c * 16) = src[c];
    }
    for (int i = tid; i < 2048; i += 256) {
        int plane = i >> 10, row = (i >> 4) & 63, c = i & 15;
        const __half* bp = plane ? Vhi : Khi;
        const uint4* src = (const uint4*)(bp + (bhS + row) * HD_);
        cpa16(sb + KV0 + (plane ? VOFF : 0) + row * LDB2 + c * 16, src + c);
    }
    CPA_COMMIT();

    float o[16][4];
    #pragma unroll
    for (int t = 0; t < 16; t++)
        #pragma unroll
        for (int e = 0; e < 4; e++) o[t][e] = 0.f;
    float m1 = -INFINITY, m2 = -INFINITY, l1 = 0.f, l2 = 0.f;
    const float scale = 0.08838834764831845f;

    int ktmax = 2 * qt + 1;
    for (int kt = 0; kt <= ktmax; kt++) {
        CPA_WAIT0();
        __syncthreads();

        if (kt < ktmax) {
            uint32_t nb = sb + KV0 + (uint32_t)((kt + 1) & 1) * KVSZ;
            for (int i = tid; i < 2048; i += 256) {
                int plane = i >> 10, row = (i >> 4) & 63, c = i & 15;
                const __half* bp = plane ? Vhi : Khi;
                const uint4* src = (const uint4*)(bp + (bhS + (size_t)(kt + 1) * 64 + row) * HD_);
                cpa16(nb + (plane ? VOFF : 0) + row * LDB2 + c * 16, src + c);
            }
            CPA_COMMIT();
        }
        uint32_t kvb = sb + KV0 + (uint32_t)(kt & 1) * KVSZ;

        float s[8][4];
        #pragma unroll
        for (int t = 0; t < 8; t++)
            #pragma unroll
            for (int e = 0; e < 4; e++) s[t][e] = 0.f;

        #pragma unroll
        for (int kk = 0; kk < 8; kk++) {
            uint32_t ah[4], al[4];
            uint32_t ra = sb + TQH + (uint32_t)(w * 16 + (l & 15)) * LDB2
                        + ((l >> 4) & 1) * 16 + kk * 32;
            ldsm4(ah, ra);
            ldsm4(al, ra + (TQL - TQH));
            #pragma unroll
            for (int g = 0; g < 4; g++) {
                uint32_t bhv[4];
                uint32_t rb = kvb
                    + (uint32_t)(16 * g + (l & 7) + ((l >> 4) & 1) * 8) * LDB2
                    + ((l >> 3) & 1) * 16 + kk * 32;
                ldsm4(bhv, rb);
                mma16816(s[2 * g],     ah, bhv);
                mma16816(s[2 * g],     al, bhv);
                mma16816(s[2 * g + 1], ah, bhv + 2);
                mma16816(s[2 * g + 1], al, bhv + 2);
            }
        }

        int r1 = qt * 128 + w * 16 + (l >> 2), r2 = r1 + 8;
        int cb = (kt << 6) + ((l & 3) << 1);
        if (kt >= 2 * qt) {
            #pragma unroll
            for (int t = 0; t < 8; t++) {
                int c0 = cb + t * 8, c1 = c0 + 1;
                s[t][0] = (c0 <= r1) ? s[t][0] * scale : -1e30f;
                s[t][1] = (c1 <= r1) ? s[t][1] * scale : -1e30f;
                s[t][2] = (c0 <= r2) ? s[t][2] * scale : -1e30f;
                s[t][3] = (c1 <= r2) ? s[t][3] * scale : -1e30f;
            }
        } else {
            #pragma unroll
            for (int t = 0; t < 8; t++)
                #pragma unroll
                for (int e = 0; e < 4; e++) s[t][e] *= scale;
        }

        float rm1 = -INFINITY, rm2 = -INFINITY;
        #pragma unroll
        for (int t = 0; t < 8; t++) {
            rm1 = fmaxf(rm1, fmaxf(s[t][0], s[t][1]));
            rm2 = fmaxf(rm2, fmaxf(s[t][2], s[t][3]));
        }
        rm1 = fmaxf(rm1, __shfl_xor_sync(0xffffffffu, rm1, 1));
        rm1 = fmaxf(rm1, __shfl_xor_sync(0xffffffffu, rm1, 2));
        rm2 = fmaxf(rm2, __shfl_xor_sync(0xffffffffu, rm2, 1));
        rm2 = fmaxf(rm2, __shfl_xor_sync(0xffffffffu, rm2, 2));
        float mn1 = fmaxf(m1, rm1), mn2 = fmaxf(m2, rm2);
        float cr1 = __expf(m1 - mn1), cr2 = __expf(m2 - mn2);
        m1 = mn1; m2 = mn2;
        float rs1 = 0.f, rs2 = 0.f;
        #pragma unroll
        for (int t = 0; t < 8; t++) {
            s[t][0] = __expf(s[t][0] - mn1);
            s[t][1] = __expf(s[t][1] - mn1);
            s[t][2] = __expf(s[t][2] - mn2);
            s[t][3] = __expf(s[t][3] - mn2);
            rs1 += s[t][0] + s[t][1];
            rs2 += s[t][2] + s[t][3];
        }
        rs1 += __shfl_xor_sync(0xffffffffu, rs1, 1);
        rs1 += __shfl_xor_sync(0xffffffffu, rs1, 2);
        rs2 += __shfl_xor_sync(0xffffffffu, rs2, 1);
        rs2 += __shfl_xor_sync(0xffffffffu, rs2, 2);
        l1 = l1 * cr1 + rs1;
        l2 = l2 * cr2 + rs2;
        #pragma unroll
        for (int t = 0; t < 16; t++) {
            o[t][0] *= cr1; o[t][1] *= cr1;
            o[t][2] *= cr2; o[t][3] *= cr2;
        }

        #pragma unroll
        for (int t = 0; t < 4; t++) {
            uint32_t pah[4], pal[4];
            float* s0 = s[2 * t];
            float* s1 = s[2 * t + 1];
            pah[0] = pack_h2(s0[0], s0[1]);
            pah[1] = pack_h2(s0[2], s0[3]);
            pah[2] = pack_h2(s1[0], s1[1]);
            pah[3] = pack_h2(s1[2], s1[3]);
            float q00 = s0[0] - __half2float(__ushort_as_half((unsigned short)(pah[0] & 0xffff)));
            float q01 = s0[1] - __half2float(__ushort_as_half((unsigned short)(pah[0] >> 16)));
            float q02 = s0[2] - __half2float(__ushort_as_half((unsigned short)(pah[1] & 0xffff)));
            float q03 = s0[3] - __half2float(__ushort_as_half((unsigned short)(pah[1] >> 16)));
            float q10 = s1[0] - __half2float(__ushort_as_half((unsigned short)(pah[2] & 0xffff)));
            float q11 = s1[1] - __half2float(__ushort_as_half((unsigned short)(pah[2] >> 16)));
            float q12 = s1[2] - __half2float(__ushort_as_half((unsigned short)(pah[3] & 0xffff)));
            float q13 = s1[3] - __half2float(__ushort_as_half((unsigned short)(pah[3] >> 16)));
            pal[0] = pack_h2(q00, q01);
            pal[1] = pack_h2(q02, q03);
            pal[2] = pack_h2(q10, q11);
            pal[3] = pack_h2(q12, q13);

            #pragma unroll
            for (int g = 0; g < 8; g++) {
                uint32_t bhv[4];
                uint32_t rb = kvb + VOFF
                    + (uint32_t)(16 * t + (l & 7) + ((l >> 3) & 1) * 8) * LDB2
                    + 32 * g + ((l >> 4) & 1) * 16;
                ldsm4t(bhv, rb);
                mma16816(o[2 * g],     pah, bhv);
                mma16816(o[2 * g],     pal, bhv);
                mma16816(o[2 * g + 1], pah, bhv + 2);
                mma16816(o[2 * g + 1], pal, bhv + 2);
            }
        }
    }

    float il1 = 1.f / l1, il2 = 1.f / l2;
    int b = bh >> 4, h = bh & (NH_ - 1);
    int sr = qt * 128 + w * 16 + (l >> 2);
    size_t base1 = ((size_t)(b * S_ + sr)) * H_ + h * HD_;
    size_t base2 = base1 + (size_t)8 * H_;
    #pragma unroll
    for (int t = 0; t < 16; t++) {
        int d = t * 8 + (l & 3) * 2;
        float v0 = o[t][0] * il1, v1 = o[t][1] * il1;
        float v2 = o[t][2] * il2, v3 = o[t][3] * il2;
        uint32_t h0 = pack_h2(v0, v1);
        float w0 = v0 - __half2float(__ushort_as_half((unsigned short)(h0 & 0xffff)));
        float w1 = v1 - __half2float(__ushort_as_half((unsigned short)(h0 >> 16)));
        uint32_t h1 = pack_h2(v2, v3);
        float w2 = v2 - __half2float(__ushort_as_half((unsigned short)(h1 & 0xffff)));
        float w3 = v3 - __half2float(__ushort_as_half((unsigned short)(h1 >> 16)));
        *(uint32_t*)&Ohi[base1 + d] = h0;
        *(uint32_t*)&Olo[base1 + d] = pack_h2(w0, w1);
        *(uint32_t*)&Ohi[base2 + d] = h1;
        *(uint32_t*)&Olo[base2 + d] = pack_h2(w2, w3);
    }
}

// ---------------------------------------------------------------------------
extern "C" void kernel_launch(void* const* d_in, const int* in_sizes, int n_in,
                              void* d_out, int out_size)
{
    const float* hidden = (const float*)d_in[0];
    const float* lastts = (const float*)d_in[1];
    const float* Wq     = (const float*)d_in[2];
    const float* Wk     = (const float*)d_in[3];
    const float* Wv     = (const float*)d_in[4];
    const float* Wo     = (const float*)d_in[5];
    const float* Wts    = (const float*)d_in[6];
    const float* tsw    = (const float*)d_in[7];
    const float* Worig  = (const float*)d_in[8];
    float* out = (float*)d_out;

    float *ts, *add, *qkv;
    __half *Ahi, *Alo, *tsHi, *tsLo, *WHi;
    __half *Qhi, *Qlo, *Khi, *Vhi;
    cudaGetSymbolAddress((void**)&ts,   g_ts);
    cudaGetSymbolAddress((void**)&add,  g_add);
    cudaGetSymbolAddress((void**)&qkv,  g_qkv);
    cudaGetSymbolAddress((void**)&Ahi,  g_Ahi);
    cudaGetSymbolAddress((void**)&Alo,  g_Alo);
    cudaGetSymbolAddress((void**)&tsHi, g_tsHi);
    cudaGetSymbolAddress((void**)&tsLo, g_tsLo);
    cudaGetSymbolAddress((void**)&WHi,  g_WHi);
    cudaGetSymbolAddress((void**)&Qhi,  g_Qhi);
    cudaGetSymbolAddress((void**)&Qlo,  g_Qlo);
    cudaGetSymbolAddress((void**)&Khi,  g_Khi);
    cudaGetSymbolAddress((void**)&Vhi,  g_Vhi);

    cudaFuncSetAttribute(gemm_mma, cudaFuncAttributeMaxDynamicSharedMemorySize, GEMM_SMEM);
    cudaFuncSetAttribute(gemm256, cudaFuncAttributeMaxDynamicSharedMemorySize, GEMM_SMEM256);
    cudaFuncSetAttribute(flash_mma, cudaFuncAttributeMaxDynamicSharedMemorySize, FLASH_SMEM2);

    dim3 tb(32, 8);
    // #0: hidden -> A planes
    convertA_kernel<<<(ROWS * H_ / 4 + 255) / 256, 256>>>(hidden, Ahi, Alo, ROWS * H_ / 4);
    // #1: Wq|Wk|Wv -> contiguous transposed fp16
    convertBT3_hi<<<dim3(64, 64, 3), tb>>>(Wq, Wk, Wv, WHi + WOFF_Q);
    // #2: rope tables
    init_invf_kernel<<<1, 64>>>();
    // #3 (profiled): fused QKV GEMM M=4096 N=6144 K=2048
    gemm256<<<dim3(48, 16), 512, GEMM_SMEM256>>>(Ahi, Alo, WHi + WOFF_Q, qkv, 2048, 6144);
    // ts pipeline
    convertBT_hi<<<dim3(64, 16), tb>>>(Wts, 512, 2048, WHi + WOFF_TS);
    gemm_mma<<<dim3(4, 32), 256, GEMM_SMEM>>>(Ahi, Alo, WHi + WOFF_TS, ts, 2048, 512);
    ts_rowops_kernel<<<ROWS, 512>>>(lastts, tsw, ts, tsHi, tsLo);
    convertBT_hi<<<dim3(16, 128), tb>>>(Worig, 6144, 512, WHi + WOFF_OR);
    gemm256<<<dim3(32, 16), 512, GEMM_SMEM256>>>(tsHi, tsLo, WHi + WOFF_OR, add, 512, 4096);
    // RoPE (+add) + transpose
    int tot = ROWS * NH_ * 64;
    rope_transpose_kernel<<<(tot + 255) / 256, 256>>>(qkv, add, Qhi, Qlo, Khi, Vhi);
    // flash attention (double-buffered K/V)
    flash_mma<<<dim3(S_ / 128, B_ * NH_), 256, FLASH_SMEM2>>>(Qhi, Qlo, Khi, Vhi,
                                                              Ahi, Alo);
    // output projection
    convertBT_hi<<<dim3(64, 64), tb>>>(Wo, 2048, 2048, WHi + WOFF_O);
    gemm256<<<dim3(16, 16), 512, GEMM_SMEM256>>>(Ahi, Alo, WHi + WOFF_O, out, 2048, 2048);
}

// round 15
// speedup vs baseline: 1.2399x; 1.0415x over previous
#include <cuda_runtime.h>
#include <cuda_fp16.h>
#include <math.h>
#include <stdint.h>

#define B_   2
#define S_   2048
#define H_   2048
#define NH_  16
#define HD_  128
#define TS_  512
#define ROWS (B_*S_)        // 4096
#define KIDX 460

// ------------------------- mma.sync helpers (baseline PTX) -----------------
__device__ __forceinline__ uint32_t smem_u32(const void* p) {
    uint32_t a;
    asm("{ .reg .u64 t; cvta.to.shared.u64 t,%1; cvt.u32.u64 %0,t; }" : "=r"(a) : "l"(p));
    return a;
}
__device__ __forceinline__ void ldsm4(uint32_t* r, uint32_t addr) {
    asm volatile("ldmatrix.sync.aligned.m8n8.x4.shared.b16 {%0,%1,%2,%3},[%4];"
        : "=r"(r[0]), "=r"(r[1]), "=r"(r[2]), "=r"(r[3]) : "r"(addr));
}
__device__ __forceinline__ void ldsm4t(uint32_t* r, uint32_t addr) {
    asm volatile("ldmatrix.sync.aligned.m8n8.x4.trans.shared.b16 {%0,%1,%2,%3},[%4];"
        : "=r"(r[0]), "=r"(r[1]), "=r"(r[2]), "=r"(r[3]) : "r"(addr));
}
__device__ __forceinline__ void mma16816(float* c, const uint32_t* a, const uint32_t* b) {
    asm volatile(
        "mma.sync.aligned.m16n8k16.row.col.f32.f16.f16.f32 "
        "{%0,%1,%2,%3},{%4,%5,%6,%7},{%8,%9},{%0,%1,%2,%3};"
        : "+f"(c[0]), "+f"(c[1]), "+f"(c[2]), "+f"(c[3])
        : "r"(a[0]), "r"(a[1]), "r"(a[2]), "r"(a[3]), "r"(b[0]), "r"(b[1]));
}
__device__ __forceinline__ uint32_t pack_h2(float a, float b) {
    __half ha = __float2half_rn(a), hb = __float2half_rn(b);
    return (uint32_t)__half_as_ushort(ha) | ((uint32_t)__half_as_ushort(hb) << 16);
}
__device__ __forceinline__ void split_store(float v, __half* hi, __half* lo, size_t idx) {
    __half h = __float2half_rn(v);
    hi[idx] = h;
    lo[idx] = __float2half_rn(v - __half2float(h));
}
__device__ __forceinline__ void cpa16(uint32_t dst, const void* src) {
    asm volatile("cp.async.cg.shared.global [%0],[%1],16;" :: "r"(dst), "l"(src));
}
#define CPA_COMMIT() asm volatile("cp.async.commit_group;" ::: "memory")
#define CPA_WAIT1()  asm volatile("cp.async.wait_group 1;" ::: "memory")
#define CPA_WAIT0()  asm volatile("cp.async.wait_group 0;" ::: "memory")

// ---------------- scratch (device globals) ---------------------------------
__device__ float g_ts[(size_t)ROWS * TS_];
__device__ float g_add[(size_t)ROWS * 4096];
__device__ float g_qkv[(size_t)ROWS * 6144];
__device__ float g_invf[64];

__device__ __half g_Ahi[(size_t)ROWS * H_];     // hidden, later attn-out
__device__ __half g_Alo[(size_t)ROWS * H_];
__device__ __half g_tsHi[(size_t)ROWS * TS_];
__device__ __half g_tsLo[(size_t)ROWS * TS_];
__device__ __half g_Qhi[(size_t)ROWS * H_];
__device__ __half g_Qlo[(size_t)ROWS * H_];
__device__ __half g_Khi[(size_t)ROWS * H_];
__device__ __half g_Vhi[(size_t)ROWS * H_];

#define WOFF_Q  ((size_t)0)
#define WOFF_K  ((size_t)4194304)
#define WOFF_V  ((size_t)8388608)
#define WOFF_O  ((size_t)12582912)
#define WOFF_TS ((size_t)16777216)
#define WOFF_OR ((size_t)17825792)
#define WTOTAL  ((size_t)19922944)
__device__ __half g_WHi[WTOTAL];

__global__ void init_invf_kernel() {
    int d = threadIdx.x;
    if (d < 64) g_invf[d] = (float)exp(-(double)d * (9.210340371976184 / 64.0));
}

// ---------------- convert kernels ------------------------------------------
__global__ void convertA_kernel(const float* __restrict__ src,
                                __half* __restrict__ hi,
                                __half* __restrict__ lo, int n4)
{
    int i = blockIdx.x * blockDim.x + threadIdx.x;
    if (i >= n4) return;
    float4 v = ((const float4*)src)[i];
    __half h0 = __float2half_rn(v.x);
    __half h1 = __float2half_rn(v.y);
    __half h2 = __float2half_rn(v.z);
    __half h3 = __float2half_rn(v.w);
    __half l0 = __float2half_rn(v.x - __half2float(h0));
    __half l1 = __float2half_rn(v.y - __half2float(h1));
    __half l2 = __float2half_rn(v.z - __half2float(h2));
    __half l3 = __float2half_rn(v.w - __half2float(h3));
    ushort4 hv = make_ushort4(__half_as_ushort(h0), __half_as_ushort(h1),
                              __half_as_ushort(h2), __half_as_ushort(h3));
    ushort4 lv = make_ushort4(__half_as_ushort(l0), __half_as_ushort(l1),
                              __half_as_ushort(l2), __half_as_ushort(l3));
    ((ushort4*)hi)[i] = hv;
    ((ushort4*)lo)[i] = lv;
}

// src [K][ld] fp32 -> dst [N][Kdim] fp16 (transposed, hi only)
__global__ void convertBT_hi(const float* __restrict__ src, int ld, int Kdim,
                             __half* __restrict__ hi)
{
    __shared__ float t[32][33];
    int tx = threadIdx.x, ty = threadIdx.y;
    int k0 = blockIdx.x * 32, n0 = blockIdx.y * 32;
    #pragma unroll
    for (int i = 0; i < 4; i++)
        t[ty + 8 * i][tx] = src[(size_t)(k0 + ty + 8 * i) * ld + n0 + tx];
    __syncthreads();
    #pragma unroll
    for (int i = 0; i < 4; i++) {
        float v = t[tx][ty + 8 * i];
        hi[(size_t)(n0 + ty + 8 * i) * Kdim + k0 + tx] = __float2half_rn(v);
    }
}

// three 2048x2048 weights -> one contiguous [6144][2048] fp16 transposed
__global__ void convertBT3_hi(const float* __restrict__ W0,
                              const float* __restrict__ W1,
                              const float* __restrict__ W2,
                              __half* __restrict__ hi)
{
    __shared__ float t[32][33];
    const float* src = (blockIdx.z == 0) ? W0 : (blockIdx.z == 1) ? W1 : W2;
    __half* dst = hi + (size_t)blockIdx.z * 4194304;
    int tx = threadIdx.x, ty = threadIdx.y;
    int k0 = blockIdx.x * 32, n0 = blockIdx.y * 32;
    #pragma unroll
    for (int i = 0; i < 4; i++)
        t[ty + 8 * i][tx] = src[(size_t)(k0 + ty + 8 * i) * 2048 + n0 + tx];
    __syncthreads();
    #pragma unroll
    for (int i = 0; i < 4; i++) {
        float v = t[tx][ty + 8 * i];
        dst[(size_t)(n0 + ty + 8 * i) * 2048 + k0 + tx] = __float2half_rn(v);
    }
}

// ============= 128x128 HMMA GEMM (2-stage), A split / B hi =================
#define BUFSZ  30720
#define GEMM_SMEM (2*BUFSZ)

__global__ __launch_bounds__(256) void gemm_mma(
    const __half* __restrict__ Ahi, const __half* __restrict__ Alo,
    const __half* __restrict__ Bhi,
    float* __restrict__ C, int K, int N)
{
    extern __shared__ char smc[];
    uint32_t sb = smem_u32(smc);
    int tid = threadIdx.x, lane = tid & 31, wid = tid >> 5;
    int wm = wid >> 2, wn = wid & 3;
    int tile_n = blockIdx.x * 128, tile_m = blockIdx.y * 128;

    int lrow = tid & 127, hf = tid >> 7;
    const uint4* Ag = (const uint4*)((hf ? Alo : Ahi) + (size_t)(tile_m + lrow) * K);
    const uint4* Bg = (const uint4*)(Bhi + (size_t)(tile_n + lrow) * K);
    uint32_t dstA = sb + hf * 10240 + lrow * 80;
    uint32_t dstB = sb + 20480 + lrow * 80;

    float acc[4][4][4];
    #pragma unroll
    for (int i = 0; i < 4; i++)
        #pragma unroll
        for (int j = 0; j < 4; j++)
            #pragma unroll
            for (int e = 0; e < 4; e++) acc[i][j][e] = 0.f;

    int nch = K >> 5;
    #pragma unroll
    for (int p = 0; p < 2; p++) {
        #pragma unroll
        for (int j = 0; j < 4; j++) {
            cpa16(dstA + p * BUFSZ + j * 16, Ag + p * 4 + j);
            if (hf == 0) cpa16(dstB + p * BUFSZ + j * 16, Bg + p * 4 + j);
        }
        CPA_COMMIT();
    }

    for (int c = 0; c < nch; c++) {
        if (c + 1 < nch) { CPA_WAIT1(); } else { CPA_WAIT0(); }
        __syncthreads();

        uint32_t base = sb + (c & 1) * BUFSZ;
        #pragma unroll
        for (int s = 0; s < 2; s++) {
            uint32_t bfr[4][2];
            #pragma unroll
            for (int jp = 0; jp < 2; jp++) {
                uint32_t nloc = (uint32_t)(wn * 32 + jp * 16 + ((lane >> 4) & 1) * 8 + (lane & 7));
                uint32_t off = 20480 + nloc * 80 + s * 32 + ((lane >> 3) & 1) * 16;
                uint32_t t[4];
                ldsm4(t, base + off);
                bfr[jp * 2][0] = t[0]; bfr[jp * 2][1] = t[1];
                bfr[jp * 2 + 1][0] = t[2]; bfr[jp * 2 + 1][1] = t[3];
            }
            #pragma unroll
            for (int i = 0; i < 4; i++) {
                uint32_t ra = (uint32_t)(wm * 64 + i * 16 + (lane & 7) + ((lane >> 3) & 1) * 8) * 80
                            + s * 32 + ((lane >> 4) & 1) * 16;
                uint32_t ah[4], al[4];
                ldsm4(ah, base + ra);
                ldsm4(al, base + 10240 + ra);
                #pragma unroll
                for (int j = 0; j < 4; j++) {
                    mma16816(acc[i][j], ah, bfr[j]);
                    mma16816(acc[i][j], al, bfr[j]);
                }
            }
        }
        __syncthreads();

        if (c + 2 < nch) {
            uint32_t dA = dstA + (c & 1) * BUFSZ;
            uint32_t dB = dstB + (c & 1) * BUFSZ;
            const uint4* a = Ag + (size_t)(c + 2) * 4;
            const uint4* b = Bg + (size_t)(c + 2) * 4;
            #pragma unroll
            for (int j = 0; j < 4; j++) {
                cpa16(dA + j * 16, a + j);
                if (hf == 0) cpa16(dB + j * 16, b + j);
            }
            CPA_COMMIT();
        }
    }

    #pragma unroll
    for (int i = 0; i < 4; i++) {
        int row = tile_m + wm * 64 + i * 16 + (lane >> 2);
        #pragma unroll
        for (int j = 0; j < 4; j++) {
            int loc = wn * 32 + j * 8 + (lane & 3) * 2;
            *(float2*)&C[(size_t)row * N + tile_n + loc] =
                make_float2(acc[i][j][0], acc[i][j][1]);
            *(float2*)&C[(size_t)(row + 8) * N + tile_n + loc] =
                make_float2(acc[i][j][2], acc[i][j][3]);
        }
    }
}

// ===== 256x128 HMMA GEMM, 3-stage cp.async, 512 thr/16 warps, 1 sync/chunk =
// stage: Ahi[0,20480) Alo[20480,40960) Bh[40960,51200)
#define STG256   51200
#define GEMM_SMEM256 (3*STG256)      // 153600

__global__ __launch_bounds__(512) void gemm256(
    const __half* __restrict__ Ahi, const __half* __restrict__ Alo,
    const __half* __restrict__ Bhi,
    float* __restrict__ C, int K, int N)
{
    extern __shared__ char smc[];
    uint32_t sb = smem_u32(smc);
    int tid = threadIdx.x, lane = tid & 31, wid = tid >> 5;
    int wm = wid >> 2, wn = wid & 3;        // 4x4 warps, warp tile 64x32
    int tile_n = blockIdx.x * 128, tile_m = blockIdx.y * 256;

    int arow = tid >> 1, aj = (tid & 1) * 2;
    const uint4* AgHi = (const uint4*)(Ahi + (size_t)(tile_m + arow) * K) + aj;
    const uint4* AgLo = (const uint4*)(Alo + (size_t)(tile_m + arow) * K) + aj;
    int brow = tid >> 2, bj = tid & 3;
    const uint4* Bg = (const uint4*)(Bhi + (size_t)(tile_n + brow) * K) + bj;
    uint32_t dA0 = sb + (uint32_t)arow * 80 + aj * 16;
    uint32_t dA1 = sb + 20480 + (uint32_t)arow * 80 + aj * 16;
    uint32_t dB  = sb + 40960 + (uint32_t)brow * 80 + bj * 16;

    float acc[4][4][4];
    #pragma unroll
    for (int i = 0; i < 4; i++)
        #pragma unroll
        for (int j = 0; j < 4; j++)
            #pragma unroll
            for (int e = 0; e < 4; e++) acc[i][j][e] = 0.f;

    int nch = K >> 5;
    // prologue: chunks 0,1 -> stages 0,1
    #pragma unroll
    for (int p = 0; p < 2; p++) {
        uint32_t o = p * STG256;
        cpa16(dA0 + o,      AgHi + p * 4);
        cpa16(dA0 + o + 16, AgHi + p * 4 + 1);
        cpa16(dA1 + o,      AgLo + p * 4);
        cpa16(dA1 + o + 16, AgLo + p * 4 + 1);
        cpa16(dB + o,       Bg + p * 4);
        CPA_COMMIT();
    }

    int st_pf = 2, st_cp = 0;
    for (int c = 0; c < nch; c++) {
        if (c + 1 < nch) { CPA_WAIT1(); } else { CPA_WAIT0(); }
        __syncthreads();   // single barrier per chunk

        // prefetch chunk c+2 into the stage freed by chunk c-1
        if (c + 2 < nch) {
            uint32_t o = (uint32_t)st_pf * STG256;
            const uint4* a0 = AgHi + (size_t)(c + 2) * 4;
            const uint4* a1 = AgLo + (size_t)(c + 2) * 4;
            const uint4* b  = Bg   + (size_t)(c + 2) * 4;
            cpa16(dA0 + o,      a0);
            cpa16(dA0 + o + 16, a0 + 1);
            cpa16(dA1 + o,      a1);
            cpa16(dA1 + o + 16, a1 + 1);
            cpa16(dB + o,       b);
            CPA_COMMIT();
            if (++st_pf == 3) st_pf = 0;
        }

        uint32_t base = sb + (uint32_t)st_cp * STG256;
        if (++st_cp == 3) st_cp = 0;
        #pragma unroll
        for (int s = 0; s < 2; s++) {
            uint32_t ah[4][4], al[4][4];
            #pragma unroll
            for (int i = 0; i < 4; i++) {
                uint32_t ra = (uint32_t)(wm * 64 + i * 16 + (lane & 7) + ((lane >> 3) & 1) * 8) * 80
                            + s * 32 + ((lane >> 4) & 1) * 16;
                ldsm4(ah[i], base + ra);
                ldsm4(al[i], base + 20480 + ra);
            }
            #pragma unroll
            for (int jp = 0; jp < 2; jp++) {
                uint32_t nloc = (uint32_t)(wn * 32 + jp * 16 + ((lane >> 4) & 1) * 8 + (lane & 7));
                uint32_t off = 40960 + nloc * 80 + s * 32 + ((lane >> 3) & 1) * 16;
                uint32_t tb[4];
                ldsm4(tb, base + off);
                #pragma unroll
                for (int i = 0; i < 4; i++) {
                    mma16816(acc[i][jp * 2],     ah[i], tb);
                    mma16816(acc[i][jp * 2],     al[i], tb);
                    mma16816(acc[i][jp * 2 + 1], ah[i], tb + 2);
                    mma16816(acc[i][jp * 2 + 1], al[i], tb + 2);
                }
            }
        }
    }

    #pragma unroll
    for (int i = 0; i < 4; i++) {
        int row = tile_m + wm * 64 + i * 16 + (lane >> 2);
        #pragma unroll
        for (int j = 0; j < 4; j++) {
            int loc = wn * 32 + j * 8 + (lane & 3) * 2;
            *(float2*)&C[(size_t)row * N + tile_n + loc] =
                make_float2(acc[i][j][0], acc[i][j][1]);
            *(float2*)&C[(size_t)(row + 8) * N + tile_n + loc] =
                make_float2(acc[i][j][2], acc[i][j][3]);
        }
    }
}

// -------- blend + rmsnorm + exact k-th + relu-shift; writes fp16 planes ----
__global__ __launch_bounds__(512) void ts_rowops_kernel(
    const float* __restrict__ last, const float* __restrict__ w,
    const float* __restrict__ ts,
    __half* __restrict__ tsHi, __half* __restrict__ tsLo)
{
    __shared__ float sv[512];
    __shared__ float rbuf[512];
    int row = blockIdx.x;
    int j = threadIdx.x;
    size_t idx = (size_t)row * TS_ + j;

    float x = 0.5f * ts[idx] + 0.5f * last[idx];
    rbuf[j] = x * x;
    __syncthreads();
    #pragma unroll
    for (int s2 = 256; s2 > 0; s2 >>= 1) {
        if (j < s2) rbuf[j] += rbuf[j + s2];
        __syncthreads();
    }
    float var = rbuf[0] * (1.f / 512.f);
    float y = x * rsqrtf(var + 1e-6f) * w[j];
    sv[j] = y;
    __syncthreads();

    for (int k = 2; k <= 512; k <<= 1) {
        for (int jj = k >> 1; jj > 0; jj >>= 1) {
            int ixj = j ^ jj;
            if (ixj > j) {
                float a = sv[j], b = sv[ixj];
                bool asc = ((j & k) == 0);
                if (asc ? (a > b) : (a < b)) { sv[j] = b; sv[ixj] = a; }
            }
            __syncthreads();
        }
    }
    float kth = sv[KIDX - 1];
    split_store(fmaxf(y - kth, 0.f), tsHi, tsLo, idx);
}

// ------- RoPE + add + transpose to head-major fp16 planes [B,NH,S,HD] -----
__global__ void rope_transpose_kernel(
    const float* __restrict__ qkv, const float* __restrict__ add,
    __half* __restrict__ Qhi, __half* __restrict__ Qlo,
    __half* __restrict__ Khi, __half* __restrict__ Vhi)
{
    int i = blockIdx.x * blockDim.x + threadIdx.x;
    if (i >= ROWS * NH_ * 64) return;
    int d = i & 63;
    int h = (i >> 6) & (NH_ - 1);
    int row = i >> 10;
    int b = row >> 11;
    int s = row & (S_ - 1);

    float inv = g_invf[d];
    float ang = (float)s * inv;
    float cs, sn;
    sincosf(ang, &sn, &cs);

    size_t src = (size_t)row * 6144 + h * HD_ + d;
    size_t arow = (size_t)row * 4096 + h * HD_ + d;
    float qa0 = add[arow],        qa1 = add[arow + 64];
    float ka0 = add[arow + 2048], ka1 = add[arow + 2048 + 64];
    float q0 = qkv[src] + qa0,           q1 = qkv[src + 64] + qa1;
    float k0 = qkv[src + 2048] + ka0,    k1 = qkv[src + 2048 + 64] + ka1;
    float v0 = qkv[src + 4096] + ka0,    v1 = qkv[src + 4096 + 64] + ka1;
    size_t dst = ((size_t)(b * NH_ + h) * S_ + s) * HD_ + d;
    split_store(q0 * cs - q1 * sn, Qhi, Qlo, dst);
    split_store(q1 * cs + q0 * sn, Qhi, Qlo, dst + 64);
    Khi[dst]      = __float2half_rn(k0 * cs - k1 * sn);
    Khi[dst + 64] = __float2half_rn(k1 * cs + k0 * sn);
    Vhi[dst]      = __float2half_rn(v0);
    Vhi[dst + 64] = __float2half_rn(v1);
}

// ---------------- flash attention, K/V double-buffered via cp.async --------
#define LDB2  272
#define TQH   0
#define TQL   34816
#define KV0   69632
#define VOFF  17408
#define KVSZ  34816
#define FLASH_SMEM2 139264

__global__ __launch_bounds__(256) void flash_mma(
    const __half* __restrict__ Qhi, const __half* __restrict__ Qlo,
    const __half* __restrict__ Khi, const __half* __restrict__ Vhi,
    __half* __restrict__ Ohi, __half* __restrict__ Olo)
{
    extern __shared__ char sm[];
    uint32_t sb = smem_u32(sm);
    int tid = threadIdx.x, l = tid & 31, w = tid >> 5;
    int qt = (int)gridDim.x - 1 - (int)blockIdx.x;
    int bh = blockIdx.y;
    size_t bhS = (size_t)bh * S_;

    for (int i = tid; i < 4096; i += 256) {
        int plane = i >> 11, row = (i >> 4) & 127, c = i & 15;
        const uint4* src = (const uint4*)((plane ? Qlo : Qhi) + (bhS + (size_t)qt * 128 + row) * HD_);
        *(uint4*)(sm + (plane ? TQL : TQH) + row * LDB2 + c * 16) = src[c];
    }
    for (int i = tid; i < 2048; i += 256) {
        int plane = i >> 10, row = (i >> 4) & 63, c = i & 15;
        const __half* bp = plane ? Vhi : Khi;
        const uint4* src = (const uint4*)(bp + (bhS + row) * HD_);
        cpa16(sb + KV0 + (plane ? VOFF : 0) + row * LDB2 + c * 16, src + c);
    }
    CPA_COMMIT();

    float o[16][4];
    #pragma unroll
    for (int t = 0; t < 16; t++)
        #pragma unroll
        for (int e = 0; e < 4; e++) o[t][e] = 0.f;
    float m1 = -INFINITY, m2 = -INFINITY, l1 = 0.f, l2 = 0.f;
    const float scale = 0.08838834764831845f;

    int ktmax = 2 * qt + 1;
    for (int kt = 0; kt <= ktmax; kt++) {
        CPA_WAIT0();
        __syncthreads();

        if (kt < ktmax) {
            uint32_t nb = sb + KV0 + (uint32_t)((kt + 1) & 1) * KVSZ;
            for (int i = tid; i < 2048; i += 256) {
                int plane = i >> 10, row = (i >> 4) & 63, c = i & 15;
                const __half* bp = plane ? Vhi : Khi;
                const uint4* src = (const uint4*)(bp + (bhS + (size_t)(kt + 1) * 64 + row) * HD_);
                cpa16(nb + (plane ? VOFF : 0) + row * LDB2 + c * 16, src + c);
            }
            CPA_COMMIT();
        }
        uint32_t kvb = sb + KV0 + (uint32_t)(kt & 1) * KVSZ;

        float s[8][4];
        #pragma unroll
        for (int t = 0; t < 8; t++)
            #pragma unroll
            for (int e = 0; e < 4; e++) s[t][e] = 0.f;

        #pragma unroll
        for (int kk = 0; kk < 8; kk++) {
            uint32_t ah[4], al[4];
            uint32_t ra = sb + TQH + (uint32_t)(w * 16 + (l & 15)) * LDB2
                        + ((l >> 4) & 1) * 16 + kk * 32;
            ldsm4(ah, ra);
            ldsm4(al, ra + (TQL - TQH));
            #pragma unroll
            for (int g = 0; g < 4; g++) {
                uint32_t bhv[4];
                uint32_t rb = kvb
                    + (uint32_t)(16 * g + (l & 7) + ((l >> 4) & 1) * 8) * LDB2
                    + ((l >> 3) & 1) * 16 + kk * 32;
                ldsm4(bhv, rb);
                mma16816(s[2 * g],     ah, bhv);
                mma16816(s[2 * g],     al, bhv);
                mma16816(s[2 * g + 1], ah, bhv + 2);
                mma16816(s[2 * g + 1], al, bhv + 2);
            }
        }

        int r1 = qt * 128 + w * 16 + (l >> 2), r2 = r1 + 8;
        int cb = (kt << 6) + ((l & 3) << 1);
        if (kt >= 2 * qt) {
            #pragma unroll
            for (int t = 0; t < 8; t++) {
                int c0 = cb + t * 8, c1 = c0 + 1;
                s[t][0] = (c0 <= r1) ? s[t][0] * scale : -1e30f;
                s[t][1] = (c1 <= r1) ? s[t][1] * scale : -1e30f;
                s[t][2] = (c0 <= r2) ? s[t][2] * scale : -1e30f;
                s[t][3] = (c1 <= r2) ? s[t][3] * scale : -1e30f;
            }
        } else {
            #pragma unroll
            for (int t = 0; t < 8; t++)
                #pragma unroll
                for (int e = 0; e < 4; e++) s[t][e] *= scale;
        }

        float rm1 = -INFINITY, rm2 = -INFINITY;
        #pragma unroll
        for (int t = 0; t < 8; t++) {
            rm1 = fmaxf(rm1, fmaxf(s[t][0], s[t][1]));
            rm2 = fmaxf(rm2, fmaxf(s[t][2], s[t][3]));
        }
        rm1 = fmaxf(rm1, __shfl_xor_sync(0xffffffffu, rm1, 1));
        rm1 = fmaxf(rm1, __shfl_xor_sync(0xffffffffu, rm1, 2));
        rm2 = fmaxf(rm2, __shfl_xor_sync(0xffffffffu, rm2, 1));
        rm2 = fmaxf(rm2, __shfl_xor_sync(0xffffffffu, rm2, 2));
        float mn1 = fmaxf(m1, rm1), mn2 = fmaxf(m2, rm2);
        float cr1 = __expf(m1 - mn1), cr2 = __expf(m2 - mn2);
        m1 = mn1; m2 = mn2;
        float rs1 = 0.f, rs2 = 0.f;
        #pragma unroll
        for (int t = 0; t < 8; t++) {
            s[t][0] = __expf(s[t][0] - mn1);
            s[t][1] = __expf(s[t][1] - mn1);
            s[t][2] = __expf(s[t][2] - mn2);
            s[t][3] = __expf(s[t][3] - mn2);
            rs1 += s[t][0] + s[t][1];
            rs2 += s[t][2] + s[t][3];
        }
        rs1 += __shfl_xor_sync(0xffffffffu, rs1, 1);
        rs1 += __shfl_xor_sync(0xffffffffu, rs1, 2);
        rs2 += __shfl_xor_sync(0xffffffffu, rs2, 1);
        rs2 += __shfl_xor_sync(0xffffffffu, rs2, 2);
        l1 = l1 * cr1 + rs1;
        l2 = l2 * cr2 + rs2;
        #pragma unroll
        for (int t = 0; t < 16; t++) {
            o[t][0] *= cr1; o[t][1] *= cr1;
            o[t][2] *= cr2; o[t][3] *= cr2;
        }

        #pragma unroll
        for (int t = 0; t < 4; t++) {
            uint32_t pah[4], pal[4];
            float* s0 = s[2 * t];
            float* s1 = s[2 * t + 1];
            pah[0] = pack_h2(s0[0], s0[1]);
            pah[1] = pack_h2(s0[2], s0[3]);
            pah[2] = pack_h2(s1[0], s1[1]);
            pah[3] = pack_h2(s1[2], s1[3]);
            float q00 = s0[0] - __half2float(__ushort_as_half((unsigned short)(pah[0] & 0xffff)));
            float q01 = s0[1] - __half2float(__ushort_as_half((unsigned short)(pah[0] >> 16)));
            float q02 = s0[2] - __half2float(__ushort_as_half((unsigned short)(pah[1] & 0xffff)));
            float q03 = s0[3] - __half2float(__ushort_as_half((unsigned short)(pah[1] >> 16)));
            float q10 = s1[0] - __half2float(__ushort_as_half((unsigned short)(pah[2] & 0xffff)));
            float q11 = s1[1] - __half2float(__ushort_as_half((unsigned short)(pah[2] >> 16)));
            float q12 = s1[2] - __half2float(__ushort_as_half((unsigned short)(pah[3] & 0xffff)));
            float q13 = s1[3] - __half2float(__ushort_as_half((unsigned short)(pah[3] >> 16)));
            pal[0] = pack_h2(q00, q01);
            pal[1] = pack_h2(q02, q03);
            pal[2] = pack_h2(q10, q11);
            pal[3] = pack_h2(q12, q13);

            #pragma unroll
            for (int g = 0; g < 8; g++) {
                uint32_t bhv[4];
                uint32_t rb = kvb + VOFF
                    + (uint32_t)(16 * t + (l & 7) + ((l >> 3) & 1) * 8) * LDB2
                    + 32 * g + ((l >> 4) & 1) * 16;
                ldsm4t(bhv, rb);
                mma16816(o[2 * g],     pah, bhv);
                mma16816(o[2 * g],     pal, bhv);
                mma16816(o[2 * g + 1], pah, bhv + 2);
                mma16816(o[2 * g + 1], pal, bhv + 2);
            }
        }
    }

    float il1 = 1.f / l1, il2 = 1.f / l2;
    int b = bh >> 4, h = bh & (NH_ - 1);
    int sr = qt * 128 + w * 16 + (l >> 2);
    size_t base1 = ((size_t)(b * S_ + sr)) * H_ + h * HD_;
    size_t base2 = base1 + (size_t)8 * H_;
    #pragma unroll
    for (int t = 0; t < 16; t++) {
        int d = t * 8 + (l & 3) * 2;
        float v0 = o[t][0] * il1, v1 = o[t][1] * il1;
        float v2 = o[t][2] * il2, v3 = o[t][3] * il2;
        uint32_t h0 = pack_h2(v0, v1);
        float w0 = v0 - __half2float(__ushort_as_half((unsigned short)(h0 & 0xffff)));
        float w1 = v1 - __half2float(__ushort_as_half((unsigned short)(h0 >> 16)));
        uint32_t h1 = pack_h2(v2, v3);
        float w2 = v2 - __half2float(__ushort_as_half((unsigned short)(h1 & 0xffff)));
        float w3 = v3 - __half2float(__ushort_as_half((unsigned short)(h1 >> 16)));
        *(uint32_t*)&Ohi[base1 + d] = h0;
        *(uint32_t*)&Olo[base1 + d] = pack_h2(w0, w1);
        *(uint32_t*)&Ohi[base2 + d] = h1;
        *(uint32_t*)&Olo[base2 + d] = pack_h2(w2, w3);
    }
}

// ---------------------------------------------------------------------------
extern "C" void kernel_launch(void* const* d_in, const int* in_sizes, int n_in,
                              void* d_out, int out_size)
{
    const float* hidden = (const float*)d_in[0];
    const float* lastts = (const float*)d_in[1];
    const float* Wq     = (const float*)d_in[2];
    const float* Wk     = (const float*)d_in[3];
    const float* Wv     = (const float*)d_in[4];
    const float* Wo     = (const float*)d_in[5];
    const float* Wts    = (const float*)d_in[6];
    const float* tsw    = (const float*)d_in[7];
    const float* Worig  = (const float*)d_in[8];
    float* out = (float*)d_out;

    float *ts, *add, *qkv;
    __half *Ahi, *Alo, *tsHi, *tsLo, *WHi;
    __half *Qhi, *Qlo, *Khi, *Vhi;
    cudaGetSymbolAddress((void**)&ts,   g_ts);
    cudaGetSymbolAddress((void**)&add,  g_add);
    cudaGetSymbolAddress((void**)&qkv,  g_qkv);
    cudaGetSymbolAddress((void**)&Ahi,  g_Ahi);
    cudaGetSymbolAddress((void**)&Alo,  g_Alo);
    cudaGetSymbolAddress((void**)&tsHi, g_tsHi);
    cudaGetSymbolAddress((void**)&tsLo, g_tsLo);
    cudaGetSymbolAddress((void**)&WHi,  g_WHi);
    cudaGetSymbolAddress((void**)&Qhi,  g_Qhi);
    cudaGetSymbolAddress((void**)&Qlo,  g_Qlo);
    cudaGetSymbolAddress((void**)&Khi,  g_Khi);
    cudaGetSymbolAddress((void**)&Vhi,  g_Vhi);

    cudaFuncSetAttribute(gemm_mma, cudaFuncAttributeMaxDynamicSharedMemorySize, GEMM_SMEM);
    cudaFuncSetAttribute(gemm256, cudaFuncAttributeMaxDynamicSharedMemorySize, GEMM_SMEM256);
    cudaFuncSetAttribute(flash_mma, cudaFuncAttributeMaxDynamicSharedMemorySize, FLASH_SMEM2);

    dim3 tb(32, 8);
    // #0: hidden -> A planes
    convertA_kernel<<<(ROWS * H_ / 4 + 255) / 256, 256>>>(hidden, Ahi, Alo, ROWS * H_ / 4);
    // #1: Wq|Wk|Wv -> contiguous transposed fp16
    convertBT3_hi<<<dim3(64, 64, 3), tb>>>(Wq, Wk, Wv, WHi + WOFF_Q);
    // #2: rope tables
    init_invf_kernel<<<1, 64>>>();
    // #3 (profiled): fused QKV GEMM M=4096 N=6144 K=2048
    gemm256<<<dim3(48, 16), 512, GEMM_SMEM256>>>(Ahi, Alo, WHi + WOFF_Q, qkv, 2048, 6144);
    // ts pipeline
    convertBT_hi<<<dim3(64, 16), tb>>>(Wts, 512, 2048, WHi + WOFF_TS);
    gemm_mma<<<dim3(4, 32), 256, GEMM_SMEM>>>(Ahi, Alo, WHi + WOFF_TS, ts, 2048, 512);
    ts_rowops_kernel<<<ROWS, 512>>>(lastts, tsw, ts, tsHi, tsLo);
    convertBT_hi<<<dim3(16, 128), tb>>>(Worig, 6144, 512, WHi + WOFF_OR);
    gemm256<<<dim3(32, 16), 512, GEMM_SMEM256>>>(tsHi, tsLo, WHi + WOFF_OR, add, 512, 4096);
    // RoPE (+add) + transpose
    int tot = ROWS * NH_ * 64;
    rope_transpose_kernel<<<(tot + 255) / 256, 256>>>(qkv, add, Qhi, Qlo, Khi, Vhi);
    // flash attention (double-buffered K/V)
    flash_mma<<<dim3(S_ / 128, B_ * NH_), 256, FLASH_SMEM2>>>(Qhi, Qlo, Khi, Vhi,
                                                              Ahi, Alo);
    // output projection
    convertBT_hi<<<dim3(64, 64), tb>>>(Wo, 2048, 2048, WHi + WOFF_O);
    gemm256<<<dim3(16, 16), 512, GEMM_SMEM256>>>(Ahi, Alo, WHi + WOFF_O, out, 2048, 2048);
}